// round 1
// baseline (speedup 1.0000x reference)
#include <cuda_runtime.h>

#define BATCH   8
#define SEQ     4096
#define DIM     64
#define DS      16
#define CHUNK   64
#define NCHUNK  (SEQ / CHUNK)        // 64
#define ROWS    (BATCH * SEQ)        // 32768
#define NBLK_M  (ROWS / 64)          // 512

// Scratch (device globals; no allocations allowed)
__device__ float g_A [ROWS * 256];           // per-timestep A_t, row-major [row][i*16+l]
__device__ float g_Bx[ROWS * DS];            // per-timestep Bx_t
__device__ float g_P [BATCH * NCHUNK * 256]; // per-chunk cumulative transition
__device__ float g_v [BATCH * NCHUNK * DS];  // per-chunk aggregate input
__device__ float g_h0[BATCH * NCHUNK * DS];  // state entering each chunk

// ---------------------------------------------------------------------------
// Kernel 1a: A = X @ W_A + b_A      ([32768,64] @ [64,256])
// block = 256 thr, tile 64(M) x 64(N), each thread 4x4 outputs
// ---------------------------------------------------------------------------
__global__ __launch_bounds__(256) void k_projA(const float* __restrict__ x,
                                               const float* __restrict__ W,
                                               const float* __restrict__ bias) {
    __shared__ float Xs[DIM * 68];   // Xs[k][m] (transposed), pad 68
    __shared__ float Ws[DIM * 68];   // Ws[k][j]
    const int tid = threadIdx.x;
    const int m0 = blockIdx.x * 64;
    const int n0 = blockIdx.y * 64;

#pragma unroll
    for (int it = 0; it < 16; it++) {
        int idx = it * 256 + tid;
        int a = idx >> 6, b = idx & 63;
        // X: m=a, k=b  (coalesced over k)
        Xs[b * 68 + a] = x[(m0 + a) * DIM + b];
        // W: k=a, j=b  (coalesced over j)
        Ws[a * 68 + b] = W[a * 256 + n0 + b];
    }
    __syncthreads();

    const int ty = tid >> 4, tx = tid & 15;
    float acc[4][4];
#pragma unroll
    for (int j = 0; j < 4; j++) {
        float bv = bias[n0 + tx * 4 + j];
#pragma unroll
        for (int i = 0; i < 4; i++) acc[i][j] = bv;
    }
#pragma unroll 8
    for (int k = 0; k < DIM; k++) {
        float4 av = *(const float4*)&Xs[k * 68 + ty * 4];
        float4 bv = *(const float4*)&Ws[k * 68 + tx * 4];
        float a4[4] = {av.x, av.y, av.z, av.w};
        float b4[4] = {bv.x, bv.y, bv.z, bv.w};
#pragma unroll
        for (int i = 0; i < 4; i++)
#pragma unroll
            for (int j = 0; j < 4; j++) acc[i][j] += a4[i] * b4[j];
    }
#pragma unroll
    for (int i = 0; i < 4; i++) {
        float4 st = {acc[i][0], acc[i][1], acc[i][2], acc[i][3]};
        *(float4*)&g_A[(long)(m0 + ty * 4 + i) * 256 + n0 + tx * 4] = st;
    }
}

// ---------------------------------------------------------------------------
// Kernel 1b: Bm = X @ W_B + b_B, then Bx[row,n] = sum_d Bm[row,n,d]*x[row,d]
// grid (512, 16): each block handles one n-group (64 d-cols) for 64 rows
// ---------------------------------------------------------------------------
__global__ __launch_bounds__(256) void k_projB(const float* __restrict__ x,
                                               const float* __restrict__ W,
                                               const float* __restrict__ bias) {
    __shared__ float Xs[DIM * 68];
    __shared__ float Ws[DIM * 68];
    const int tid = threadIdx.x;
    const int m0 = blockIdx.x * 64;
    const int nblk = blockIdx.y;       // n in [0,16)
    const int n0 = nblk * 64;

#pragma unroll
    for (int it = 0; it < 16; it++) {
        int idx = it * 256 + tid;
        int a = idx >> 6, b = idx & 63;
        Xs[b * 68 + a] = x[(m0 + a) * DIM + b];
        Ws[a * 68 + b] = W[a * 1024 + n0 + b];
    }
    __syncthreads();

    const int ty = tid >> 4, tx = tid & 15;
    float acc[4][4];
#pragma unroll
    for (int j = 0; j < 4; j++) {
        float bv = bias[n0 + tx * 4 + j];
#pragma unroll
        for (int i = 0; i < 4; i++) acc[i][j] = bv;
    }
#pragma unroll 8
    for (int k = 0; k < DIM; k++) {
        float4 av = *(const float4*)&Xs[k * 68 + ty * 4];
        float4 bv = *(const float4*)&Ws[k * 68 + tx * 4];
        float a4[4] = {av.x, av.y, av.z, av.w};
        float b4[4] = {bv.x, bv.y, bv.z, bv.w};
#pragma unroll
        for (int i = 0; i < 4; i++)
#pragma unroll
            for (int j = 0; j < 4; j++) acc[i][j] += a4[i] * b4[j];
    }
    // contract with x over d (columns of this tile), reduce over tx lanes
    float px[4];
#pragma unroll
    for (int i = 0; i < 4; i++) {
        float s = 0.f;
#pragma unroll
        for (int j = 0; j < 4; j++)
            s += acc[i][j] * Xs[(tx * 4 + j) * 68 + (ty * 4 + i)];
        px[i] = s;
    }
#pragma unroll
    for (int i = 0; i < 4; i++) {
        px[i] += __shfl_down_sync(0xffffffffu, px[i], 8, 16);
        px[i] += __shfl_down_sync(0xffffffffu, px[i], 4, 16);
        px[i] += __shfl_down_sync(0xffffffffu, px[i], 2, 16);
        px[i] += __shfl_down_sync(0xffffffffu, px[i], 1, 16);
    }
    if (tx == 0) {
#pragma unroll
        for (int i = 0; i < 4; i++)
            g_Bx[(long)(m0 + ty * 4 + i) * DS + nblk] = px[i];
    }
}

// ---------------------------------------------------------------------------
// Kernel 1c: per-chunk cumulative P = A_{L-1}...A_0 and v (input aggregate)
// one block per (batch, chunk); 256 thr = (i,l) pairs of 16x16
// ---------------------------------------------------------------------------
__global__ __launch_bounds__(256) void k_chunk() {
    __shared__ float Pbuf[2][16][17];
    __shared__ float vbuf[2][16];
    __shared__ float As[16][17];
    const int tid = threadIdx.x;
    const int i = tid >> 4, l = tid & 15;
    const int bc = blockIdx.x;                 // b*NCHUNK + c
    const long base = (long)bc * CHUNK * 256;

    Pbuf[0][i][l] = (i == l) ? 1.f : 0.f;
    if (tid < 16) vbuf[0][tid] = 0.f;
    __syncthreads();

    float a = g_A[base + tid];
    for (int t = 0; t < CHUNK; t++) {
        As[i][l] = a;
        __syncthreads();
        float a_next = (t + 1 < CHUNK) ? g_A[base + (long)(t + 1) * 256 + tid] : 0.f;
        const int cur = t & 1, nxt = cur ^ 1;
        float s = 0.f;
#pragma unroll
        for (int q = 0; q < 16; q++) s += As[i][q] * Pbuf[cur][q][l];
        Pbuf[nxt][i][l] = s;
        if (l == 0) {
            float vn = g_Bx[(long)(bc * CHUNK + t) * DS + i];
#pragma unroll
            for (int q = 0; q < 16; q++) vn += As[i][q] * vbuf[cur][q];
            vbuf[nxt][i] = vn;
        }
        __syncthreads();
        a = a_next;
    }
    g_P[(long)bc * 256 + tid] = Pbuf[0][i][l];   // CHUNK even -> final in buf 0
    if (tid < 16) g_v[bc * DS + tid] = vbuf[0][tid];
}

// ---------------------------------------------------------------------------
// Kernel 2: sequential over chunks (per batch); 1 block, warp per batch
// ---------------------------------------------------------------------------
__global__ __launch_bounds__(256) void k_scan() {
    const int b = threadIdx.x >> 5;
    const int lane = threadIdx.x & 31;
    if (lane >= 16) return;
    float h = 0.f;
    for (int c = 0; c < NCHUNK; c++) {
        const int bc = b * NCHUNK + c;
        g_h0[bc * DS + lane] = h;
        const float4* Pr = (const float4*)&g_P[(long)bc * 256 + lane * 16];
        float4 p0 = Pr[0], p1 = Pr[1], p2 = Pr[2], p3 = Pr[3];
        float pv[16] = {p0.x, p0.y, p0.z, p0.w, p1.x, p1.y, p1.z, p1.w,
                        p2.x, p2.y, p2.z, p2.w, p3.x, p3.y, p3.z, p3.w};
        float hn = g_v[bc * DS + lane];
#pragma unroll
        for (int q = 0; q < 16; q++)
            hn += pv[q] * __shfl_sync(0x0000ffffu, h, q, 16);
        h = hn;
    }
}

// ---------------------------------------------------------------------------
// Kernel 3: within-chunk replay + fused output projection
//   out[t,d] = sum_{k,n} x[t,k] h[t,n] W_C[k, n*64+d] + sum_n h[t,n] b_C[n*64+d]
// via Z[q=k*16+n, t] = x[t,k]*h[t,n]; out = Z^T @ W_C'   (K = 1024)
// ---------------------------------------------------------------------------
#define SM3_FLOATS (3 * 64 * 68 + 64 * 17 + 64 * 16 + 32)
__global__ __launch_bounds__(256) void k_out(const float* __restrict__ x,
                                             const float* __restrict__ W_C,
                                             const float* __restrict__ b_C,
                                             float* __restrict__ out) {
    extern __shared__ float sm[];
    float* Xs  = sm;                 // [64][68]  Xs[k][t]
    float* Ws  = Xs + 64 * 68;       // [64][68]  Ws[qq][d]
    float* Zs  = Ws + 64 * 68;       // [64][68]  Zs[qq][t]
    float* Hs  = Zs + 64 * 68;       // [64][17]  Hs[t][n]
    float* Bxs = Hs + 64 * 17;       // [64][16]
    float* hb  = Bxs + 64 * 16;      // [2][16]

    const int tid = threadIdx.x;
    const int bc = blockIdx.x;
    const long rowbase = (long)bc * CHUNK;

#pragma unroll
    for (int it = 0; it < 16; it++) {
        int idx = it * 256 + tid;
        int t = idx >> 6, k = idx & 63;
        Xs[k * 68 + t] = x[(rowbase + t) * DIM + k];
    }
#pragma unroll
    for (int it = 0; it < 4; it++) {
        int idx = it * 256 + tid;
        Bxs[idx] = g_Bx[rowbase * DS + idx];
    }
    if (tid < 16) hb[tid] = g_h0[bc * DS + tid];
    __syncthreads();

    // replay: h_{t} = A_t h_{t-1} + Bx_t ; record into Hs
    const int i16 = tid >> 4, l16 = tid & 15;
    float a = g_A[rowbase * 256 + tid];
    for (int t = 0; t < CHUNK; t++) {
        float a_next = (t + 1 < CHUNK) ? g_A[rowbase * 256 + (long)(t + 1) * 256 + tid] : 0.f;
        const int cur = t & 1;
        float prod = a * hb[cur * 16 + l16];
        prod += __shfl_down_sync(0xffffffffu, prod, 8, 16);
        prod += __shfl_down_sync(0xffffffffu, prod, 4, 16);
        prod += __shfl_down_sync(0xffffffffu, prod, 2, 16);
        prod += __shfl_down_sync(0xffffffffu, prod, 1, 16);
        if (l16 == 0) {
            float hv = prod + Bxs[t * 16 + i16];
            hb[(cur ^ 1) * 16 + i16] = hv;
            Hs[t * 17 + i16] = hv;
        }
        __syncthreads();
        a = a_next;
    }

    // out tile [64 t x 64 d] = Z^T @ W_C'
    const int ty = tid >> 4, tx = tid & 15;
    float acc[4][4];
#pragma unroll
    for (int i = 0; i < 4; i++)
#pragma unroll
        for (int j = 0; j < 4; j++) acc[i][j] = 0.f;

    for (int kt = 0; kt < 16; kt++) {
#pragma unroll
        for (int it = 0; it < 16; it++) {
            int idx = it * 256 + tid;
            int qq = idx >> 6, dd = idx & 63;
            int q = kt * 64 + qq;
            Ws[qq * 68 + dd] = W_C[(q >> 4) * 1024 + (q & 15) * 64 + dd];
            // Zs build reuses same idx decomposition: qq, t=dd
            Zs[qq * 68 + dd] = Xs[(q >> 4) * 68 + dd] * Hs[dd * 17 + (q & 15)];
        }
        __syncthreads();
#pragma unroll 8
        for (int qq = 0; qq < 64; qq++) {
            float4 zv = *(const float4*)&Zs[qq * 68 + ty * 4];
            float4 wv = *(const float4*)&Ws[qq * 68 + tx * 4];
            float z4[4] = {zv.x, zv.y, zv.z, zv.w};
            float w4[4] = {wv.x, wv.y, wv.z, wv.w};
#pragma unroll
            for (int i = 0; i < 4; i++)
#pragma unroll
                for (int j = 0; j < 4; j++) acc[i][j] += z4[i] * w4[j];
        }
        __syncthreads();
    }

    // bias term: += sum_n Hs[t][n] * b_C[n*64+d]  (stage b_C in Zs)
#pragma unroll
    for (int it = 0; it < 4; it++) {
        int idx = it * 256 + tid;
        int n = idx >> 6, dd = idx & 63;
        Zs[n * 68 + dd] = b_C[n * 64 + dd];
    }
    __syncthreads();
#pragma unroll
    for (int i = 0; i < 4; i++)
#pragma unroll
        for (int j = 0; j < 4; j++) {
            float s = acc[i][j];
#pragma unroll
            for (int n = 0; n < 16; n++)
                s += Hs[(ty * 4 + i) * 17 + n] * Zs[n * 68 + tx * 4 + j];
            acc[i][j] = s;
        }

#pragma unroll
    for (int i = 0; i < 4; i++) {
        float4 st = {acc[i][0], acc[i][1], acc[i][2], acc[i][3]};
        *(float4*)&out[(rowbase + ty * 4 + i) * DIM + tx * 4] = st;
    }
}

// ---------------------------------------------------------------------------
extern "C" void kernel_launch(void* const* d_in, const int* in_sizes, int n_in,
                              void* d_out, int out_size) {
    const float* x   = (const float*)d_in[0];
    const float* W_A = (const float*)d_in[1];
    const float* b_A = (const float*)d_in[2];
    const float* W_B = (const float*)d_in[3];
    const float* b_B = (const float*)d_in[4];
    const float* W_C = (const float*)d_in[5];
    const float* b_C = (const float*)d_in[6];
    float* out = (float*)d_out;

    const int smem3 = SM3_FLOATS * sizeof(float);
    cudaFuncSetAttribute(k_out, cudaFuncAttributeMaxDynamicSharedMemorySize, smem3);

    k_projA<<<dim3(NBLK_M, 4), 256>>>(x, W_A, b_A);
    k_projB<<<dim3(NBLK_M, 16), 256>>>(x, W_B, b_B);
    k_chunk<<<BATCH * NCHUNK, 256>>>();
    k_scan<<<1, 256>>>();
    k_out<<<BATCH * NCHUNK, 256, smem3>>>(x, W_C, b_C, out);
}

// round 2
// speedup vs baseline: 1.7210x; 1.7210x over previous
#include <cuda_runtime.h>

#define BATCH   8
#define SEQ     4096
#define DIM     64
#define DS      16
#define CHUNK   64
#define NCHUNK  (SEQ / CHUNK)        // 64
#define ROWS    (BATCH * SEQ)        // 32768

// Scratch (device globals; no allocations allowed)
__device__ float g_A [ROWS * 256];           // per-timestep A_t [row][i*16+l]
__device__ float g_Bx[ROWS * DS];            // per-timestep Bx_t
__device__ float g_P [BATCH * NCHUNK * 256]; // per-chunk cumulative transition
__device__ float g_v [BATCH * NCHUNK * DS];  // per-chunk aggregate input
__device__ float g_h0[BATCH * NCHUNK * DS];  // state entering each chunk

// ---------------------------------------------------------------------------
// helpers: tf32 convert + m16n8k8 tf32 mma
// ---------------------------------------------------------------------------
__device__ __forceinline__ float f2tf(float f) {
    unsigned u;
    asm("cvt.rna.tf32.f32 %0, %1;" : "=r"(u) : "f"(f));
    return __uint_as_float(u);
}
__device__ __forceinline__ void mma8(float* c,
                                     unsigned a0, unsigned a1, unsigned a2, unsigned a3,
                                     unsigned b0, unsigned b1) {
    asm volatile(
        "mma.sync.aligned.m16n8k8.row.col.f32.tf32.tf32.f32 "
        "{%0,%1,%2,%3},{%4,%5,%6,%7},{%8,%9},{%0,%1,%2,%3};"
        : "+f"(c[0]), "+f"(c[1]), "+f"(c[2]), "+f"(c[3])
        : "r"(a0), "r"(a1), "r"(a2), "r"(a3), "r"(b0), "r"(b1));
}
__device__ __forceinline__ unsigned fu(float f) { return __float_as_uint(f); }

// ---------------------------------------------------------------------------
// Kernel 1a (tensor): A = X @ W_A + b_A   ([32768,64] @ [64,256])
// BM=128, BN=64; 8 warps as 4(M)x2(N); warp tile 32x32; K=64 (8 ksteps)
// dyn smem: Xs[128][68] + Ws[64][68]
// ---------------------------------------------------------------------------
__global__ __launch_bounds__(256) void k_projA(const float* __restrict__ x,
                                               const float* __restrict__ W,
                                               const float* __restrict__ bias) {
    extern __shared__ float sm[];
    float* Xs = sm;             // [128][68]
    float* Ws = sm + 128 * 68;  // [64][68]
    const int tid = threadIdx.x;
    const int m0 = blockIdx.x * 128;
    const int n0 = blockIdx.y * 64;

#pragma unroll
    for (int it = 0; it < 8; it++) {           // X tile: 2048 float4
        int i4 = it * 256 + tid;
        int row = i4 >> 4, c4 = (i4 & 15) * 4;
        float4 v = *(const float4*)&x[(long)(m0 + row) * 64 + c4];
        Xs[row * 68 + c4 + 0] = f2tf(v.x);
        Xs[row * 68 + c4 + 1] = f2tf(v.y);
        Xs[row * 68 + c4 + 2] = f2tf(v.z);
        Xs[row * 68 + c4 + 3] = f2tf(v.w);
    }
#pragma unroll
    for (int it = 0; it < 4; it++) {           // W tile 64x64: 1024 float4
        int i4 = it * 256 + tid;
        int row = i4 >> 4, c4 = (i4 & 15) * 4;
        float4 v = *(const float4*)&W[(long)row * 256 + n0 + c4];
        Ws[row * 68 + c4 + 0] = f2tf(v.x);
        Ws[row * 68 + c4 + 1] = f2tf(v.y);
        Ws[row * 68 + c4 + 2] = f2tf(v.z);
        Ws[row * 68 + c4 + 3] = f2tf(v.w);
    }
    __syncthreads();

    const int wid = tid >> 5, lane = tid & 31;
    const int g = lane >> 2, tig = lane & 3;
    const int wm = wid & 3, wn = wid >> 2;
    const int mbase = wm * 32, nbase = wn * 32;

    float c[2][4][4];
#pragma unroll
    for (int mt = 0; mt < 2; mt++)
#pragma unroll
        for (int nt = 0; nt < 4; nt++)
#pragma unroll
            for (int j = 0; j < 4; j++) c[mt][nt][j] = 0.f;

#pragma unroll
    for (int ks = 0; ks < 8; ks++) {
        const int k0 = ks * 8;
        unsigned a[2][4];
#pragma unroll
        for (int mt = 0; mt < 2; mt++) {
            int r = mbase + mt * 16 + g;
            a[mt][0] = fu(Xs[r * 68 + k0 + tig]);
            a[mt][1] = fu(Xs[(r + 8) * 68 + k0 + tig]);
            a[mt][2] = fu(Xs[r * 68 + k0 + tig + 4]);
            a[mt][3] = fu(Xs[(r + 8) * 68 + k0 + tig + 4]);
        }
        unsigned b[4][2];
#pragma unroll
        for (int nt = 0; nt < 4; nt++) {
            int n = nbase + nt * 8 + g;
            b[nt][0] = fu(Ws[(k0 + tig) * 68 + n]);
            b[nt][1] = fu(Ws[(k0 + tig + 4) * 68 + n]);
        }
#pragma unroll
        for (int mt = 0; mt < 2; mt++)
#pragma unroll
            for (int nt = 0; nt < 4; nt++)
                mma8(c[mt][nt], a[mt][0], a[mt][1], a[mt][2], a[mt][3],
                     b[nt][0], b[nt][1]);
    }

#pragma unroll
    for (int mt = 0; mt < 2; mt++)
#pragma unroll
        for (int nt = 0; nt < 4; nt++) {
            int row = m0 + mbase + mt * 16 + g;
            int col = n0 + nbase + nt * 8 + tig * 2;
            float b0 = bias[col], b1 = bias[col + 1];
            *(float2*)&g_A[(long)row * 256 + col] =
                make_float2(c[mt][nt][0] + b0, c[mt][nt][1] + b1);
            *(float2*)&g_A[(long)(row + 8) * 256 + col] =
                make_float2(c[mt][nt][2] + b0, c[mt][nt][3] + b1);
        }
}

// ---------------------------------------------------------------------------
// Kernel 1b (tensor): Bm = X @ W_B + b_B fused with Bx = Bm . x
// BM=128, BN=128 (2 n-groups); 8 warps as 2(M)x4(N); warp 64x32; K=64
// dyn smem: Xs[128][68] + Ws[64][132] + red[128][4]
// ---------------------------------------------------------------------------
__global__ __launch_bounds__(256) void k_projB(const float* __restrict__ x,
                                               const float* __restrict__ W,
                                               const float* __restrict__ bias) {
    extern __shared__ float sm[];
    float* Xs  = sm;                        // [128][68]
    float* Ws  = sm + 128 * 68;             // [64][132]
    float* red = Ws + 64 * 132;             // [128][4]
    const int tid = threadIdx.x;
    const int m0 = blockIdx.x * 128;
    const int n0 = blockIdx.y * 128;

#pragma unroll
    for (int it = 0; it < 8; it++) {
        int i4 = it * 256 + tid;
        int row = i4 >> 4, c4 = (i4 & 15) * 4;
        float4 v = *(const float4*)&x[(long)(m0 + row) * 64 + c4];
        Xs[row * 68 + c4 + 0] = f2tf(v.x);
        Xs[row * 68 + c4 + 1] = f2tf(v.y);
        Xs[row * 68 + c4 + 2] = f2tf(v.z);
        Xs[row * 68 + c4 + 3] = f2tf(v.w);
    }
#pragma unroll
    for (int it = 0; it < 8; it++) {        // W tile 64x128: 2048 float4
        int i4 = it * 256 + tid;
        int row = i4 >> 5, c4 = (i4 & 31) * 4;
        float4 v = *(const float4*)&W[(long)row * 1024 + n0 + c4];
        Ws[row * 132 + c4 + 0] = f2tf(v.x);
        Ws[row * 132 + c4 + 1] = f2tf(v.y);
        Ws[row * 132 + c4 + 2] = f2tf(v.z);
        Ws[row * 132 + c4 + 3] = f2tf(v.w);
    }
    __syncthreads();

    const int wid = tid >> 5, lane = tid & 31;
    const int g = lane >> 2, tig = lane & 3;
    const int wm = wid & 1, wn = wid >> 1;    // 2 M-warps x 4 N-warps
    const int mbase = wm * 64, nbase = wn * 32;

    float c[4][4][4];
#pragma unroll
    for (int mt = 0; mt < 4; mt++)
#pragma unroll
        for (int nt = 0; nt < 4; nt++)
#pragma unroll
            for (int j = 0; j < 4; j++) c[mt][nt][j] = 0.f;

#pragma unroll
    for (int ks = 0; ks < 8; ks++) {
        const int k0 = ks * 8;
        unsigned a[4][4];
#pragma unroll
        for (int mt = 0; mt < 4; mt++) {
            int r = mbase + mt * 16 + g;
            a[mt][0] = fu(Xs[r * 68 + k0 + tig]);
            a[mt][1] = fu(Xs[(r + 8) * 68 + k0 + tig]);
            a[mt][2] = fu(Xs[r * 68 + k0 + tig + 4]);
            a[mt][3] = fu(Xs[(r + 8) * 68 + k0 + tig + 4]);
        }
        unsigned b[4][2];
#pragma unroll
        for (int nt = 0; nt < 4; nt++) {
            int n = nbase + nt * 8 + g;
            b[nt][0] = fu(Ws[(k0 + tig) * 132 + n]);
            b[nt][1] = fu(Ws[(k0 + tig + 4) * 132 + n]);
        }
#pragma unroll
        for (int mt = 0; mt < 4; mt++)
#pragma unroll
            for (int nt = 0; nt < 4; nt++)
                mma8(c[mt][nt], a[mt][0], a[mt][1], a[mt][2], a[mt][3],
                     b[nt][0], b[nt][1]);
    }

    // epilogue: Bx partials. local col d0 = nbase + nt*8 + tig*2 (+1);
    // x feature index = (d0 & 63); bias index = n0 + d0.
    float bv0[4], bv1[4];
    int dl[4];
#pragma unroll
    for (int nt = 0; nt < 4; nt++) {
        int d0 = nbase + nt * 8 + tig * 2;
        dl[nt] = d0 & 63;
        bv0[nt] = bias[n0 + d0];
        bv1[nt] = bias[n0 + d0 + 1];
    }
#pragma unroll
    for (int mt = 0; mt < 4; mt++) {
        int r0 = mbase + mt * 16 + g;
        int r1 = r0 + 8;
        float p0 = 0.f, p1 = 0.f;
#pragma unroll
        for (int nt = 0; nt < 4; nt++) {
            float x00 = Xs[r0 * 68 + dl[nt]];
            float x01 = Xs[r0 * 68 + dl[nt] + 1];
            float x10 = Xs[r1 * 68 + dl[nt]];
            float x11 = Xs[r1 * 68 + dl[nt] + 1];
            p0 += (c[mt][nt][0] + bv0[nt]) * x00 + (c[mt][nt][1] + bv1[nt]) * x01;
            p1 += (c[mt][nt][2] + bv0[nt]) * x10 + (c[mt][nt][3] + bv1[nt]) * x11;
        }
        p0 += __shfl_xor_sync(0xffffffffu, p0, 1, 4);
        p0 += __shfl_xor_sync(0xffffffffu, p0, 2, 4);
        p1 += __shfl_xor_sync(0xffffffffu, p1, 1, 4);
        p1 += __shfl_xor_sync(0xffffffffu, p1, 2, 4);
        if (tig == 0) {
            red[r0 * 4 + wn] = p0;
            red[r1 * 4 + wn] = p1;
        }
    }
    __syncthreads();
    if (tid < 256) {
        int r = tid >> 1, grp = tid & 1;
        float bx = red[r * 4 + grp * 2] + red[r * 4 + grp * 2 + 1];
        int n_idx = blockIdx.y * 2 + grp;
        g_Bx[(long)(m0 + r) * DS + n_idx] = bx;
    }
}

// ---------------------------------------------------------------------------
// Kernel 1c: per-chunk cumulative P and aggregate v (unchanged)
// ---------------------------------------------------------------------------
__global__ __launch_bounds__(256) void k_chunk() {
    __shared__ float Pbuf[2][16][17];
    __shared__ float vbuf[2][16];
    __shared__ float As[16][17];
    const int tid = threadIdx.x;
    const int i = tid >> 4, l = tid & 15;
    const int bc = blockIdx.x;
    const long base = (long)bc * CHUNK * 256;

    Pbuf[0][i][l] = (i == l) ? 1.f : 0.f;
    if (tid < 16) vbuf[0][tid] = 0.f;
    __syncthreads();

    float a = g_A[base + tid];
    for (int t = 0; t < CHUNK; t++) {
        As[i][l] = a;
        __syncthreads();
        float a_next = (t + 1 < CHUNK) ? g_A[base + (long)(t + 1) * 256 + tid] : 0.f;
        const int cur = t & 1, nxt = cur ^ 1;
        float s = 0.f;
#pragma unroll
        for (int q = 0; q < 16; q++) s += As[i][q] * Pbuf[cur][q][l];
        Pbuf[nxt][i][l] = s;
        if (l == 0) {
            float vn = g_Bx[(long)(bc * CHUNK + t) * DS + i];
#pragma unroll
            for (int q = 0; q < 16; q++) vn += As[i][q] * vbuf[cur][q];
            vbuf[nxt][i] = vn;
        }
        __syncthreads();
        a = a_next;
    }
    g_P[(long)bc * 256 + tid] = Pbuf[0][i][l];
    if (tid < 16) g_v[bc * DS + tid] = vbuf[0][tid];
}

// ---------------------------------------------------------------------------
// Kernel 2: sequential over chunks. Replicated-h registers, independent
// broadcast shuffles, prefetch next chunk's P/v.
// ---------------------------------------------------------------------------
__global__ __launch_bounds__(256) void k_scan() {
    const int b = threadIdx.x >> 5;
    const int lane = threadIdx.x & 31;
    if (b >= BATCH || lane >= 16) return;

    float h[16];
#pragma unroll
    for (int q = 0; q < 16; q++) h[q] = 0.f;
    float mine = 0.f;

    const long base = (long)b * NCHUNK;
    const float4* P0 = (const float4*)&g_P[base * 256 + lane * 16];
    float4 p0 = P0[0], p1 = P0[1], p2 = P0[2], p3 = P0[3];
    float v = g_v[base * DS + lane];

    for (int c = 0; c < NCHUNK; c++) {
        const long bc = base + c;
        g_h0[bc * DS + lane] = mine;

        float4 q0, q1, q2, q3;
        float vn = 0.f;
        if (c + 1 < NCHUNK) {
            const float4* Pn = (const float4*)&g_P[(bc + 1) * 256 + lane * 16];
            q0 = Pn[0]; q1 = Pn[1]; q2 = Pn[2]; q3 = Pn[3];
            vn = g_v[(bc + 1) * DS + lane];
        } else {
            q0 = p0; q1 = p1; q2 = p2; q3 = p3;
        }

        float s0 = v + p0.x * h[0] + p0.y * h[1] + p0.z * h[2] + p0.w * h[3];
        float s1 = p1.x * h[4] + p1.y * h[5] + p1.z * h[6] + p1.w * h[7];
        float s2 = p2.x * h[8] + p2.y * h[9] + p2.z * h[10] + p2.w * h[11];
        float s3 = p3.x * h[12] + p3.y * h[13] + p3.z * h[14] + p3.w * h[15];
        float hn = (s0 + s1) + (s2 + s3);
        mine = hn;
#pragma unroll
        for (int q = 0; q < 16; q++)
            h[q] = __shfl_sync(0x0000ffffu, hn, q, 16);

        p0 = q0; p1 = q1; p2 = q2; p3 = q3; v = vn;
    }
}

// ---------------------------------------------------------------------------
// Kernel 3 (tensor): within-chunk replay + fused output projection
//   out = Z @ W_C' + h @ b_C' ; Z[t, q=k*16+n] = x[t,k]*h[t,n]
// M=64 (chunk), N=64, K=1024 (16 k-tiles of 64)
// dyn smem: Xs[64][68] Ws[64][68] Zs[64][68] Hs[64][17] Bxs[64][16] hb[16]
// ---------------------------------------------------------------------------
#define KO_XS   0
#define KO_WS   (64 * 68)
#define KO_ZS   (2 * 64 * 68)
#define KO_HS   (3 * 64 * 68)
#define KO_BXS  (KO_HS + 64 * 17)
#define KO_HB   (KO_BXS + 64 * 16)
#define KO_SMEM (KO_HB + 16)

__device__ __forceinline__ void ko_load_ws(float* Ws, const float* __restrict__ W_C,
                                           int kt, int t0, int nthr) {
    // Ws[qq][dd] = tf32(W_C[(q>>4)*1024 + (q&15)*64 + dd]), q = kt*64+qq
    int nf4 = 1024 / nthr;   // float4s per thread (1024 total)
    for (int it = 0; it < nf4; it++) {
        int i4 = it * nthr + t0;
        int qq = i4 >> 4, c4 = (i4 & 15) * 4;
        int q = kt * 64 + qq;
        float4 v = *(const float4*)&W_C[(long)(q >> 4) * 1024 + (q & 15) * 64 + c4];
        Ws[qq * 68 + c4 + 0] = f2tf(v.x);
        Ws[qq * 68 + c4 + 1] = f2tf(v.y);
        Ws[qq * 68 + c4 + 2] = f2tf(v.z);
        Ws[qq * 68 + c4 + 3] = f2tf(v.w);
    }
}

__global__ __launch_bounds__(256) void k_out(const float* __restrict__ x,
                                             const float* __restrict__ W_C,
                                             const float* __restrict__ b_C,
                                             float* __restrict__ out) {
    extern __shared__ float sm[];
    float* Xs  = sm + KO_XS;    // [64][68] x[t][k] fp32
    float* Ws  = sm + KO_WS;    // [64][68] tf32 W_C'
    float* Zs  = sm + KO_ZS;    // [64][68] tf32 Z
    float* Hs  = sm + KO_HS;    // [64][17]
    float* Bxs = sm + KO_BXS;   // [64][16]
    float* hb  = sm + KO_HB;    // [16]

    const int tid = threadIdx.x;
    const int bc = blockIdx.x;
    const long rowbase = (long)bc * CHUNK;

#pragma unroll
    for (int it = 0; it < 4; it++) {          // X tile 64x64
        int i4 = it * 256 + tid;
        int t = i4 >> 4, c4 = (i4 & 15) * 4;
        float4 v = *(const float4*)&x[(rowbase + t) * 64 + c4];
        *(float4*)&Xs[t * 68 + c4] = v;
    }
    {
        float4 v = *(const float4*)&g_Bx[rowbase * DS + tid * 4];
        *(float4*)&Bxs[tid * 4] = v;
    }
    if (tid < 16) hb[tid] = g_h0[bc * DS + tid];
    __syncthreads();

    const int wid = tid >> 5, lane = tid & 31;

    if (wid == 0 && lane < 16) {
        // register replay: lane i computes h_i each step; h replicated
        float h[16];
#pragma unroll
        for (int q = 0; q < 16; q++) h[q] = hb[q];
        const float* Arow = &g_A[rowbase * 256 + lane * 16];
        float4 a0 = *(const float4*)&Arow[0];
        float4 a1 = *(const float4*)&Arow[4];
        float4 a2 = *(const float4*)&Arow[8];
        float4 a3 = *(const float4*)&Arow[12];
        for (int t = 0; t < CHUNK; t++) {
            float4 n0 = a0, n1 = a1, n2 = a2, n3 = a3;
            if (t + 1 < CHUNK) {
                const float* An = &g_A[(rowbase + t + 1) * 256 + lane * 16];
                n0 = *(const float4*)&An[0];
                n1 = *(const float4*)&An[4];
                n2 = *(const float4*)&An[8];
                n3 = *(const float4*)&An[12];
            }
            float s0 = Bxs[t * 16 + lane]
                     + a0.x * h[0] + a0.y * h[1] + a0.z * h[2] + a0.w * h[3];
            float s1 = a1.x * h[4] + a1.y * h[5] + a1.z * h[6] + a1.w * h[7];
            float s2 = a2.x * h[8] + a2.y * h[9] + a2.z * h[10] + a2.w * h[11];
            float s3 = a3.x * h[12] + a3.y * h[13] + a3.z * h[14] + a3.w * h[15];
            float hn = (s0 + s1) + (s2 + s3);
            Hs[t * 17 + lane] = hn;
#pragma unroll
            for (int q = 0; q < 16; q++)
                h[q] = __shfl_sync(0x0000ffffu, hn, q, 16);
            a0 = n0; a1 = n1; a2 = n2; a3 = n3;
        }
    } else if (wid >= 4) {
        ko_load_ws(Ws, W_C, 0, tid - 128, 128);   // preload k-tile 0
    }
    __syncthreads();

    const int g = lane >> 2, tig = lane & 3;
    const int wm = wid & 3, wn = wid >> 2;     // 4 M-warps x 2 N-warps
    const int t0r = wm * 16;                   // warp row base
    const int nbase = wn * 32;

    float c[4][4];
#pragma unroll
    for (int nt = 0; nt < 4; nt++)
#pragma unroll
        for (int j = 0; j < 4; j++) c[nt][j] = 0.f;

    for (int kt = 0; kt < 16; kt++) {
        if (kt > 0) ko_load_ws(Ws, W_C, kt, tid, 256);
        // build Z tile: Zs[t][qq] = tf32(x[t][kt*4 + qq>>4] * h[t][qq&15])
#pragma unroll
        for (int it = 0; it < 16; it++) {
            int idx = it * 256 + tid;
            int t = idx >> 6, qq = idx & 63;
            Zs[t * 68 + qq] =
                f2tf(Xs[t * 68 + kt * 4 + (qq >> 4)] * Hs[t * 17 + (qq & 15)]);
        }
        __syncthreads();
#pragma unroll
        for (int ks = 0; ks < 8; ks++) {
            const int k0 = ks * 8;
            unsigned a0 = fu(Zs[(t0r + g) * 68 + k0 + tig]);
            unsigned a1 = fu(Zs[(t0r + g + 8) * 68 + k0 + tig]);
            unsigned a2 = fu(Zs[(t0r + g) * 68 + k0 + tig + 4]);
            unsigned a3 = fu(Zs[(t0r + g + 8) * 68 + k0 + tig + 4]);
#pragma unroll
            for (int nt = 0; nt < 4; nt++) {
                int n = nbase + nt * 8 + g;
                unsigned b0 = fu(Ws[(k0 + tig) * 68 + n]);
                unsigned b1 = fu(Ws[(k0 + tig + 4) * 68 + n]);
                mma8(c[nt], a0, a1, a2, a3, b0, b1);
            }
        }
        __syncthreads();
    }

    // bias: stage b_C into Zs[n][68], then out += h . b_C'
    {
        int n = tid >> 4, c4 = (tid & 15) * 4;
        float4 v = *(const float4*)&b_C[n * 64 + c4];
        *(float4*)&Zs[n * 68 + c4] = v;
    }
    __syncthreads();

#pragma unroll
    for (int nt = 0; nt < 4; nt++) {
        int col = nbase + nt * 8 + tig * 2;
        int ta = t0r + g, tb = t0r + g + 8;
        float s00 = 0.f, s01 = 0.f, s10 = 0.f, s11 = 0.f;
#pragma unroll
        for (int n = 0; n < 16; n++) {
            float ha = Hs[ta * 17 + n], hbv = Hs[tb * 17 + n];
            float w0 = Zs[n * 68 + col], w1 = Zs[n * 68 + col + 1];
            s00 += ha * w0; s01 += ha * w1;
            s10 += hbv * w0; s11 += hbv * w1;
        }
        *(float2*)&out[(rowbase + ta) * 64 + col] =
            make_float2(c[nt][0] + s00, c[nt][1] + s01);
        *(float2*)&out[(rowbase + tb) * 64 + col] =
            make_float2(c[nt][2] + s10, c[nt][3] + s11);
    }
}

// ---------------------------------------------------------------------------
extern "C" void kernel_launch(void* const* d_in, const int* in_sizes, int n_in,
                              void* d_out, int out_size) {
    const float* x   = (const float*)d_in[0];
    const float* W_A = (const float*)d_in[1];
    const float* b_A = (const float*)d_in[2];
    const float* W_B = (const float*)d_in[3];
    const float* b_B = (const float*)d_in[4];
    const float* W_C = (const float*)d_in[5];
    const float* b_C = (const float*)d_in[6];
    float* out = (float*)d_out;

    const int smA = (128 * 68 + 64 * 68) * sizeof(float);              // 52224
    const int smB = (128 * 68 + 64 * 132 + 128 * 4) * sizeof(float);   // 70656
    const int smO = KO_SMEM * sizeof(float);                           // ~60.8KB
    cudaFuncSetAttribute(k_projA, cudaFuncAttributeMaxDynamicSharedMemorySize, smA);
    cudaFuncSetAttribute(k_projB, cudaFuncAttributeMaxDynamicSharedMemorySize, smB);
    cudaFuncSetAttribute(k_out,   cudaFuncAttributeMaxDynamicSharedMemorySize, smO);

    k_projA<<<dim3(ROWS / 128, 4), 256, smA>>>(x, W_A, b_A);
    k_projB<<<dim3(ROWS / 128, 8), 256, smB>>>(x, W_B, b_B);
    k_chunk<<<BATCH * NCHUNK, 256>>>();
    k_scan<<<1, 256>>>();
    k_out<<<BATCH * NCHUNK, 256, smO>>>(x, W_C, b_C, out);
}

// round 3
// speedup vs baseline: 2.1699x; 1.2608x over previous
#include <cuda_runtime.h>

#define BATCH   8
#define SEQ     4096
#define DIM     64
#define DS      16
#define CHUNK   64
#define NCHUNK  (SEQ / CHUNK)        // 64
#define ROWS    (BATCH * SEQ)        // 32768

// Scratch (device globals; no allocations allowed)
__device__ float g_A [ROWS * 256];           // per-timestep A_t [row][i*16+l]
__device__ float g_Bx[ROWS * DS];            // per-timestep Bx_t
__device__ float g_P [BATCH * NCHUNK * 256]; // per-chunk cumulative transition
__device__ float g_v [BATCH * NCHUNK * DS];  // per-chunk aggregate input
__device__ float g_h0[BATCH * NCHUNK * DS];  // state entering each chunk

// ---------------------------------------------------------------------------
// helpers: tf32 convert + m16n8k8 tf32 mma
// ---------------------------------------------------------------------------
__device__ __forceinline__ float f2tf(float f) {
    unsigned u;
    asm("cvt.rna.tf32.f32 %0, %1;" : "=r"(u) : "f"(f));
    return __uint_as_float(u);
}
__device__ __forceinline__ void mma8(float* c,
                                     unsigned a0, unsigned a1, unsigned a2, unsigned a3,
                                     unsigned b0, unsigned b1) {
    asm volatile(
        "mma.sync.aligned.m16n8k8.row.col.f32.tf32.tf32.f32 "
        "{%0,%1,%2,%3},{%4,%5,%6,%7},{%8,%9},{%0,%1,%2,%3};"
        : "+f"(c[0]), "+f"(c[1]), "+f"(c[2]), "+f"(c[3])
        : "r"(a0), "r"(a1), "r"(a2), "r"(a3), "r"(b0), "r"(b1));
}
__device__ __forceinline__ unsigned fu(float f) { return __float_as_uint(f); }

__device__ __forceinline__ void cp16(void* smem_dst, const void* gsrc) {
    unsigned s = (unsigned)__cvta_generic_to_shared(smem_dst);
    asm volatile("cp.async.ca.shared.global [%0], [%1], 16;" :: "r"(s), "l"(gsrc));
}

// ---------------------------------------------------------------------------
// Kernel 1a (tensor): A = X @ W_A + b_A   ([32768,64] @ [64,256])
// ---------------------------------------------------------------------------
__global__ __launch_bounds__(256) void k_projA(const float* __restrict__ x,
                                               const float* __restrict__ W,
                                               const float* __restrict__ bias) {
    extern __shared__ float sm[];
    float* Xs = sm;             // [128][68]
    float* Ws = sm + 128 * 68;  // [64][68]
    const int tid = threadIdx.x;
    const int m0 = blockIdx.x * 128;
    const int n0 = blockIdx.y * 64;

#pragma unroll
    for (int it = 0; it < 8; it++) {
        int i4 = it * 256 + tid;
        int row = i4 >> 4, c4 = (i4 & 15) * 4;
        float4 v = *(const float4*)&x[(long)(m0 + row) * 64 + c4];
        Xs[row * 68 + c4 + 0] = f2tf(v.x);
        Xs[row * 68 + c4 + 1] = f2tf(v.y);
        Xs[row * 68 + c4 + 2] = f2tf(v.z);
        Xs[row * 68 + c4 + 3] = f2tf(v.w);
    }
#pragma unroll
    for (int it = 0; it < 4; it++) {
        int i4 = it * 256 + tid;
        int row = i4 >> 4, c4 = (i4 & 15) * 4;
        float4 v = *(const float4*)&W[(long)row * 256 + n0 + c4];
        Ws[row * 68 + c4 + 0] = f2tf(v.x);
        Ws[row * 68 + c4 + 1] = f2tf(v.y);
        Ws[row * 68 + c4 + 2] = f2tf(v.z);
        Ws[row * 68 + c4 + 3] = f2tf(v.w);
    }
    __syncthreads();

    const int wid = tid >> 5, lane = tid & 31;
    const int g = lane >> 2, tig = lane & 3;
    const int wm = wid & 3, wn = wid >> 2;
    const int mbase = wm * 32, nbase = wn * 32;

    float c[2][4][4];
#pragma unroll
    for (int mt = 0; mt < 2; mt++)
#pragma unroll
        for (int nt = 0; nt < 4; nt++)
#pragma unroll
            for (int j = 0; j < 4; j++) c[mt][nt][j] = 0.f;

#pragma unroll
    for (int ks = 0; ks < 8; ks++) {
        const int k0 = ks * 8;
        unsigned a[2][4];
#pragma unroll
        for (int mt = 0; mt < 2; mt++) {
            int r = mbase + mt * 16 + g;
            a[mt][0] = fu(Xs[r * 68 + k0 + tig]);
            a[mt][1] = fu(Xs[(r + 8) * 68 + k0 + tig]);
            a[mt][2] = fu(Xs[r * 68 + k0 + tig + 4]);
            a[mt][3] = fu(Xs[(r + 8) * 68 + k0 + tig + 4]);
        }
        unsigned b[4][2];
#pragma unroll
        for (int nt = 0; nt < 4; nt++) {
            int n = nbase + nt * 8 + g;
            b[nt][0] = fu(Ws[(k0 + tig) * 68 + n]);
            b[nt][1] = fu(Ws[(k0 + tig + 4) * 68 + n]);
        }
#pragma unroll
        for (int mt = 0; mt < 2; mt++)
#pragma unroll
            for (int nt = 0; nt < 4; nt++)
                mma8(c[mt][nt], a[mt][0], a[mt][1], a[mt][2], a[mt][3],
                     b[nt][0], b[nt][1]);
    }

#pragma unroll
    for (int mt = 0; mt < 2; mt++)
#pragma unroll
        for (int nt = 0; nt < 4; nt++) {
            int row = m0 + mbase + mt * 16 + g;
            int col = n0 + nbase + nt * 8 + tig * 2;
            float b0 = bias[col], b1 = bias[col + 1];
            *(float2*)&g_A[(long)row * 256 + col] =
                make_float2(c[mt][nt][0] + b0, c[mt][nt][1] + b1);
            *(float2*)&g_A[(long)(row + 8) * 256 + col] =
                make_float2(c[mt][nt][2] + b0, c[mt][nt][3] + b1);
        }
}

// ---------------------------------------------------------------------------
// Kernel 1b (tensor): Bm = X @ W_B + b_B fused with Bx = Bm . x
// ---------------------------------------------------------------------------
__global__ __launch_bounds__(256) void k_projB(const float* __restrict__ x,
                                               const float* __restrict__ W,
                                               const float* __restrict__ bias) {
    extern __shared__ float sm[];
    float* Xs  = sm;                        // [128][68]
    float* Ws  = sm + 128 * 68;             // [64][132]
    float* red = Ws + 64 * 132;             // [128][4]
    const int tid = threadIdx.x;
    const int m0 = blockIdx.x * 128;
    const int n0 = blockIdx.y * 128;

#pragma unroll
    for (int it = 0; it < 8; it++) {
        int i4 = it * 256 + tid;
        int row = i4 >> 4, c4 = (i4 & 15) * 4;
        float4 v = *(const float4*)&x[(long)(m0 + row) * 64 + c4];
        Xs[row * 68 + c4 + 0] = f2tf(v.x);
        Xs[row * 68 + c4 + 1] = f2tf(v.y);
        Xs[row * 68 + c4 + 2] = f2tf(v.z);
        Xs[row * 68 + c4 + 3] = f2tf(v.w);
    }
#pragma unroll
    for (int it = 0; it < 8; it++) {
        int i4 = it * 256 + tid;
        int row = i4 >> 5, c4 = (i4 & 31) * 4;
        float4 v = *(const float4*)&W[(long)row * 1024 + n0 + c4];
        Ws[row * 132 + c4 + 0] = f2tf(v.x);
        Ws[row * 132 + c4 + 1] = f2tf(v.y);
        Ws[row * 132 + c4 + 2] = f2tf(v.z);
        Ws[row * 132 + c4 + 3] = f2tf(v.w);
    }
    __syncthreads();

    const int wid = tid >> 5, lane = tid & 31;
    const int g = lane >> 2, tig = lane & 3;
    const int wm = wid & 1, wn = wid >> 1;
    const int mbase = wm * 64, nbase = wn * 32;

    float c[4][4][4];
#pragma unroll
    for (int mt = 0; mt < 4; mt++)
#pragma unroll
        for (int nt = 0; nt < 4; nt++)
#pragma unroll
            for (int j = 0; j < 4; j++) c[mt][nt][j] = 0.f;

#pragma unroll
    for (int ks = 0; ks < 8; ks++) {
        const int k0 = ks * 8;
        unsigned a[4][4];
#pragma unroll
        for (int mt = 0; mt < 4; mt++) {
            int r = mbase + mt * 16 + g;
            a[mt][0] = fu(Xs[r * 68 + k0 + tig]);
            a[mt][1] = fu(Xs[(r + 8) * 68 + k0 + tig]);
            a[mt][2] = fu(Xs[r * 68 + k0 + tig + 4]);
            a[mt][3] = fu(Xs[(r + 8) * 68 + k0 + tig + 4]);
        }
        unsigned b[4][2];
#pragma unroll
        for (int nt = 0; nt < 4; nt++) {
            int n = nbase + nt * 8 + g;
            b[nt][0] = fu(Ws[(k0 + tig) * 132 + n]);
            b[nt][1] = fu(Ws[(k0 + tig + 4) * 132 + n]);
        }
#pragma unroll
        for (int mt = 0; mt < 4; mt++)
#pragma unroll
            for (int nt = 0; nt < 4; nt++)
                mma8(c[mt][nt], a[mt][0], a[mt][1], a[mt][2], a[mt][3],
                     b[nt][0], b[nt][1]);
    }

    float bv0[4], bv1[4];
    int dl[4];
#pragma unroll
    for (int nt = 0; nt < 4; nt++) {
        int d0 = nbase + nt * 8 + tig * 2;
        dl[nt] = d0 & 63;
        bv0[nt] = bias[n0 + d0];
        bv1[nt] = bias[n0 + d0 + 1];
    }
#pragma unroll
    for (int mt = 0; mt < 4; mt++) {
        int r0 = mbase + mt * 16 + g;
        int r1 = r0 + 8;
        float p0 = 0.f, p1 = 0.f;
#pragma unroll
        for (int nt = 0; nt < 4; nt++) {
            float x00 = Xs[r0 * 68 + dl[nt]];
            float x01 = Xs[r0 * 68 + dl[nt] + 1];
            float x10 = Xs[r1 * 68 + dl[nt]];
            float x11 = Xs[r1 * 68 + dl[nt] + 1];
            p0 += (c[mt][nt][0] + bv0[nt]) * x00 + (c[mt][nt][1] + bv1[nt]) * x01;
            p1 += (c[mt][nt][2] + bv0[nt]) * x10 + (c[mt][nt][3] + bv1[nt]) * x11;
        }
        p0 += __shfl_xor_sync(0xffffffffu, p0, 1, 4);
        p0 += __shfl_xor_sync(0xffffffffu, p0, 2, 4);
        p1 += __shfl_xor_sync(0xffffffffu, p1, 1, 4);
        p1 += __shfl_xor_sync(0xffffffffu, p1, 2, 4);
        if (tig == 0) {
            red[r0 * 4 + wn] = p0;
            red[r1 * 4 + wn] = p1;
        }
    }
    __syncthreads();
    {
        int r = tid >> 1, grp = tid & 1;
        float bx = red[r * 4 + grp * 2] + red[r * 4 + grp * 2 + 1];
        int n_idx = blockIdx.y * 2 + grp;
        g_Bx[(long)(m0 + r) * DS + n_idx] = bx;
    }
}

// ---------------------------------------------------------------------------
// Kernel 1c: per-chunk P,v via binary tree combine (6 levels, not 64 steps)
//   merge(seg0 then seg1): P = P1 P0 ; v = P1 v0 + v1
// ---------------------------------------------------------------------------
#define MSTRIDE 272
#define CK_BUFA 0
#define CK_BUFB (32 * MSTRIDE)
#define CK_VX   (2 * 32 * MSTRIDE)        // [64][16] Bx
#define CK_VA   (CK_VX + 64 * 16)         // [32][16]
#define CK_VB   (CK_VA + 32 * 16)
#define CK_SMEM (CK_VB + 32 * 16)

__global__ __launch_bounds__(256) void k_chunk() {
    extern __shared__ float sm[];
    float* bufA = sm + CK_BUFA;
    float* bufB = sm + CK_BUFB;
    float* VX   = sm + CK_VX;
    float* Va   = sm + CK_VA;
    float* Vb   = sm + CK_VB;
    const int tid = threadIdx.x;
    const int bc = blockIdx.x;
    const long rowbase = (long)bc * CHUNK;

    // stage even-index A matrices into bufA (coalesced)
#pragma unroll
    for (int it = 0; it < 8; it++) {
        int i4 = it * 256 + tid;               // 0..2047 float4s
        int m = i4 >> 6, e4 = (i4 & 63) * 4;
        *(float4*)&bufA[m * MSTRIDE + e4] =
            *(const float4*)&g_A[(rowbase + 2 * m) * 256 + e4];
    }
    // stage all 64 Bx vectors
    *(float4*)&VX[tid * 4] = *(const float4*)&g_Bx[rowbase * DS + tid * 4];
    __syncthreads();

    // Level 0: odd A rows from global x even A (smem) -> bufB
#pragma unroll
    for (int rep = 0; rep < 2; rep++) {
        int r = rep * 256 + tid;               // 0..511
        int m = r >> 4, i = r & 15;
        const float* arow = &g_A[(rowbase + 2 * m + 1) * 256 + i * 16];
        float4 a0 = *(const float4*)&arow[0];
        float4 a1 = *(const float4*)&arow[4];
        float4 a2 = *(const float4*)&arow[8];
        float4 a3 = *(const float4*)&arow[12];
        float av[16] = {a0.x, a0.y, a0.z, a0.w, a1.x, a1.y, a1.z, a1.w,
                        a2.x, a2.y, a2.z, a2.w, a3.x, a3.y, a3.z, a3.w};
        float acc[16];
#pragma unroll
        for (int l = 0; l < 16; l++) acc[l] = 0.f;
        float accv = VX[(2 * m + 1) * 16 + i];
#pragma unroll
        for (int q = 0; q < 16; q++) {
            float aq = av[q];
            float4 b0 = *(const float4*)&bufA[m * MSTRIDE + q * 16 + 0];
            float4 b1 = *(const float4*)&bufA[m * MSTRIDE + q * 16 + 4];
            float4 b2 = *(const float4*)&bufA[m * MSTRIDE + q * 16 + 8];
            float4 b3 = *(const float4*)&bufA[m * MSTRIDE + q * 16 + 12];
            acc[0]  += aq * b0.x; acc[1]  += aq * b0.y;
            acc[2]  += aq * b0.z; acc[3]  += aq * b0.w;
            acc[4]  += aq * b1.x; acc[5]  += aq * b1.y;
            acc[6]  += aq * b1.z; acc[7]  += aq * b1.w;
            acc[8]  += aq * b2.x; acc[9]  += aq * b2.y;
            acc[10] += aq * b2.z; acc[11] += aq * b2.w;
            acc[12] += aq * b3.x; acc[13] += aq * b3.y;
            acc[14] += aq * b3.z; acc[15] += aq * b3.w;
            accv += aq * VX[2 * m * 16 + q];
        }
#pragma unroll
        for (int l4 = 0; l4 < 4; l4++)
            *(float4*)&bufB[m * MSTRIDE + i * 16 + l4 * 4] =
                make_float4(acc[l4 * 4], acc[l4 * 4 + 1],
                            acc[l4 * 4 + 2], acc[l4 * 4 + 3]);
        Vb[m * 16 + i] = accv;
    }
    __syncthreads();

    // Levels 1..5 entirely in smem, ping-pong
    float* src = bufB; float* dst = bufA;
    float* vs = Vb;    float* vd = Va;
#pragma unroll
    for (int lev = 1; lev <= 5; lev++) {
        int nmerge = 32 >> lev;                // 16,8,4,2,1
        int rows = nmerge * 16;
        if (tid < rows) {
            int m = tid >> 4, i = tid & 15;
            const float* a1p = &src[(2 * m + 1) * MSTRIDE + i * 16];
            float4 a0 = *(const float4*)&a1p[0];
            float4 a1 = *(const float4*)&a1p[4];
            float4 a2 = *(const float4*)&a1p[8];
            float4 a3 = *(const float4*)&a1p[12];
            float av[16] = {a0.x, a0.y, a0.z, a0.w, a1.x, a1.y, a1.z, a1.w,
                            a2.x, a2.y, a2.z, a2.w, a3.x, a3.y, a3.z, a3.w};
            float acc[16];
#pragma unroll
            for (int l = 0; l < 16; l++) acc[l] = 0.f;
            float accv = vs[(2 * m + 1) * 16 + i];
#pragma unroll
            for (int q = 0; q < 16; q++) {
                float aq = av[q];
                const float* bp = &src[2 * m * MSTRIDE + q * 16];
                float4 b0 = *(const float4*)&bp[0];
                float4 b1 = *(const float4*)&bp[4];
                float4 b2 = *(const float4*)&bp[8];
                float4 b3 = *(const float4*)&bp[12];
                acc[0]  += aq * b0.x; acc[1]  += aq * b0.y;
                acc[2]  += aq * b0.z; acc[3]  += aq * b0.w;
                acc[4]  += aq * b1.x; acc[5]  += aq * b1.y;
                acc[6]  += aq * b1.z; acc[7]  += aq * b1.w;
                acc[8]  += aq * b2.x; acc[9]  += aq * b2.y;
                acc[10] += aq * b2.z; acc[11] += aq * b2.w;
                acc[12] += aq * b3.x; acc[13] += aq * b3.y;
                acc[14] += aq * b3.z; acc[15] += aq * b3.w;
                accv += aq * vs[2 * m * 16 + q];
            }
#pragma unroll
            for (int l4 = 0; l4 < 4; l4++)
                *(float4*)&dst[m * MSTRIDE + i * 16 + l4 * 4] =
                    make_float4(acc[l4 * 4], acc[l4 * 4 + 1],
                                acc[l4 * 4 + 2], acc[l4 * 4 + 3]);
            vd[m * 16 + i] = accv;
        }
        __syncthreads();
        float* t = src; src = dst; dst = t;
        float* tv = vs; vs = vd; vd = tv;
    }

    // result in src / vs
    g_P[(long)bc * 256 + tid] = src[tid];
    if (tid < 16) g_v[bc * DS + tid] = vs[tid];
}

// ---------------------------------------------------------------------------
// Kernel 2: inter-chunk scan. One block per batch; cp.async ring, depth 4.
// ---------------------------------------------------------------------------
#define RING_ROW 20                 // floats per lane row (80B, 16B aligned)
#define RING_STAGE (16 * RING_ROW + 16)   // P rows + v

__global__ __launch_bounds__(32) void k_scan() {
    __shared__ float ring[4][RING_STAGE];
    const int b = blockIdx.x;
    const int lane = threadIdx.x;
    const long base = (long)b * NCHUNK;

    // prime 4 stages
#pragma unroll
    for (int c = 0; c < 4; c++) {
        int slot = c & 3;
        if (lane < 16) {
            const float* src = &g_P[(base + c) * 256 + lane * 16];
#pragma unroll
            for (int j = 0; j < 4; j++)
                cp16(&ring[slot][lane * RING_ROW + j * 4], src + j * 4);
        }
        if (lane < 4)
            cp16(&ring[slot][16 * RING_ROW + lane * 4],
                 &g_v[(base + c) * DS + lane * 4]);
        asm volatile("cp.async.commit_group;");
    }

    float h[16];
#pragma unroll
    for (int q = 0; q < 16; q++) h[q] = 0.f;
    float mine = 0.f;

    for (int c = 0; c < NCHUNK; c++) {
        asm volatile("cp.async.wait_group 3;");
        __syncwarp();
        float hn = 0.f;
        if (lane < 16) {
            g_h0[(base + c) * DS + lane] = mine;
            const float* R = &ring[c & 3][lane * RING_ROW];
            float4 p0 = *(const float4*)&R[0];
            float4 p1 = *(const float4*)&R[4];
            float4 p2 = *(const float4*)&R[8];
            float4 p3 = *(const float4*)&R[12];
            float v = ring[c & 3][16 * RING_ROW + lane];
            float s0 = v + p0.x * h[0] + p0.y * h[1] + p0.z * h[2] + p0.w * h[3];
            float s1 = p1.x * h[4] + p1.y * h[5] + p1.z * h[6] + p1.w * h[7];
            float s2 = p2.x * h[8] + p2.y * h[9] + p2.z * h[10] + p2.w * h[11];
            float s3 = p3.x * h[12] + p3.y * h[13] + p3.z * h[14] + p3.w * h[15];
            hn = (s0 + s1) + (s2 + s3);
            mine = hn;
        }
#pragma unroll
        for (int q = 0; q < 16; q++)
            h[q] = __shfl_sync(0xffffffffu, hn, q);
        // refill this slot for chunk c+4 (or commit an empty group to keep
        // the wait_group accounting correct)
        if (c + 4 < NCHUNK) {
            int slot = c & 3;
            if (lane < 16) {
                const float* src = &g_P[(base + c + 4) * 256 + lane * 16];
#pragma unroll
                for (int j = 0; j < 4; j++)
                    cp16(&ring[slot][lane * RING_ROW + j * 4], src + j * 4);
            }
            if (lane < 4)
                cp16(&ring[slot][16 * RING_ROW + lane * 4],
                     &g_v[(base + c + 4) * DS + lane * 4]);
        }
        asm volatile("cp.async.commit_group;");
    }
}

// ---------------------------------------------------------------------------
// Kernel 3 (tensor): within-chunk replay + fused output projection
// ---------------------------------------------------------------------------
#define KO_XS   0
#define KO_WS   (64 * 68)
#define KO_ZS   (2 * 64 * 68)
#define KO_HS   (3 * 64 * 68)
#define KO_BXS  (KO_HS + 64 * 17)
#define KO_HB   (KO_BXS + 64 * 16)
#define KO_SMEM (KO_HB + 16)

__device__ __forceinline__ void ko_load_ws(float* Ws, const float* __restrict__ W_C,
                                           int kt, int t0, int nthr) {
    int nf4 = 1024 / nthr;
    for (int it = 0; it < nf4; it++) {
        int i4 = it * nthr + t0;
        int qq = i4 >> 4, c4 = (i4 & 15) * 4;
        int q = kt * 64 + qq;
        float4 v = *(const float4*)&W_C[(long)(q >> 4) * 1024 + (q & 15) * 64 + c4];
        Ws[qq * 68 + c4 + 0] = f2tf(v.x);
        Ws[qq * 68 + c4 + 1] = f2tf(v.y);
        Ws[qq * 68 + c4 + 2] = f2tf(v.z);
        Ws[qq * 68 + c4 + 3] = f2tf(v.w);
    }
}

__global__ __launch_bounds__(256) void k_out(const float* __restrict__ x,
                                             const float* __restrict__ W_C,
                                             const float* __restrict__ b_C,
                                             float* __restrict__ out) {
    extern __shared__ float sm[];
    float* Xs  = sm + KO_XS;
    float* Ws  = sm + KO_WS;
    float* Zs  = sm + KO_ZS;
    float* Hs  = sm + KO_HS;
    float* Bxs = sm + KO_BXS;
    float* hb  = sm + KO_HB;

    const int tid = threadIdx.x;
    const int bc = blockIdx.x;
    const long rowbase = (long)bc * CHUNK;

#pragma unroll
    for (int it = 0; it < 4; it++) {
        int i4 = it * 256 + tid;
        int t = i4 >> 4, c4 = (i4 & 15) * 4;
        float4 v = *(const float4*)&x[(rowbase + t) * 64 + c4];
        *(float4*)&Xs[t * 68 + c4] = v;
    }
    {
        float4 v = *(const float4*)&g_Bx[rowbase * DS + tid * 4];
        *(float4*)&Bxs[tid * 4] = v;
    }
    if (tid < 16) hb[tid] = g_h0[bc * DS + tid];
    __syncthreads();

    const int wid = tid >> 5, lane = tid & 31;

    if (wid == 0 && lane < 16) {
        float h[16];
#pragma unroll
        for (int q = 0; q < 16; q++) h[q] = hb[q];
        const float* Arow = &g_A[rowbase * 256 + lane * 16];
        float4 a0 = *(const float4*)&Arow[0];
        float4 a1 = *(const float4*)&Arow[4];
        float4 a2 = *(const float4*)&Arow[8];
        float4 a3 = *(const float4*)&Arow[12];
        for (int t = 0; t < CHUNK; t++) {
            float4 n0 = a0, n1 = a1, n2 = a2, n3 = a3;
            if (t + 1 < CHUNK) {
                const float* An = &g_A[(rowbase + t + 1) * 256 + lane * 16];
                n0 = *(const float4*)&An[0];
                n1 = *(const float4*)&An[4];
                n2 = *(const float4*)&An[8];
                n3 = *(const float4*)&An[12];
            }
            float s0 = Bxs[t * 16 + lane]
                     + a0.x * h[0] + a0.y * h[1] + a0.z * h[2] + a0.w * h[3];
            float s1 = a1.x * h[4] + a1.y * h[5] + a1.z * h[6] + a1.w * h[7];
            float s2 = a2.x * h[8] + a2.y * h[9] + a2.z * h[10] + a2.w * h[11];
            float s3 = a3.x * h[12] + a3.y * h[13] + a3.z * h[14] + a3.w * h[15];
            float hn = (s0 + s1) + (s2 + s3);
            Hs[t * 17 + lane] = hn;
#pragma unroll
            for (int q = 0; q < 16; q++)
                h[q] = __shfl_sync(0x0000ffffu, hn, q, 16);
            a0 = n0; a1 = n1; a2 = n2; a3 = n3;
        }
    } else if (wid >= 4) {
        ko_load_ws(Ws, W_C, 0, tid - 128, 128);
    }
    __syncthreads();

    const int g = lane >> 2, tig = lane & 3;
    const int wm = wid & 3, wn = wid >> 2;
    const int t0r = wm * 16;
    const int nbase = wn * 32;

    float c[4][4];
#pragma unroll
    for (int nt = 0; nt < 4; nt++)
#pragma unroll
        for (int j = 0; j < 4; j++) c[nt][j] = 0.f;

    for (int kt = 0; kt < 16; kt++) {
        if (kt > 0) ko_load_ws(Ws, W_C, kt, tid, 256);
#pragma unroll
        for (int it = 0; it < 16; it++) {
            int idx = it * 256 + tid;
            int t = idx >> 6, qq = idx & 63;
            Zs[t * 68 + qq] =
                f2tf(Xs[t * 68 + kt * 4 + (qq >> 4)] * Hs[t * 17 + (qq & 15)]);
        }
        __syncthreads();
#pragma unroll
        for (int ks = 0; ks < 8; ks++) {
            const int k0 = ks * 8;
            unsigned a0 = fu(Zs[(t0r + g) * 68 + k0 + tig]);
            unsigned a1 = fu(Zs[(t0r + g + 8) * 68 + k0 + tig]);
            unsigned a2 = fu(Zs[(t0r + g) * 68 + k0 + tig + 4]);
            unsigned a3 = fu(Zs[(t0r + g + 8) * 68 + k0 + tig + 4]);
#pragma unroll
            for (int nt = 0; nt < 4; nt++) {
                int n = nbase + nt * 8 + g;
                unsigned b0 = fu(Ws[(k0 + tig) * 68 + n]);
                unsigned b1 = fu(Ws[(k0 + tig + 4) * 68 + n]);
                mma8(c[nt], a0, a1, a2, a3, b0, b1);
            }
        }
        __syncthreads();
    }

    {
        int n = tid >> 4, c4 = (tid & 15) * 4;
        float4 v = *(const float4*)&b_C[n * 64 + c4];
        *(float4*)&Zs[n * 68 + c4] = v;
    }
    __syncthreads();

#pragma unroll
    for (int nt = 0; nt < 4; nt++) {
        int col = nbase + nt * 8 + tig * 2;
        int ta = t0r + g, tb = t0r + g + 8;
        float s00 = 0.f, s01 = 0.f, s10 = 0.f, s11 = 0.f;
#pragma unroll
        for (int n = 0; n < 16; n++) {
            float ha = Hs[ta * 17 + n], hbv = Hs[tb * 17 + n];
            float w0 = Zs[n * 68 + col], w1 = Zs[n * 68 + col + 1];
            s00 += ha * w0; s01 += ha * w1;
            s10 += hbv * w0; s11 += hbv * w1;
        }
        *(float2*)&out[(rowbase + ta) * 64 + col] =
            make_float2(c[nt][0] + s00, c[nt][1] + s01);
        *(float2*)&out[(rowbase + tb) * 64 + col] =
            make_float2(c[nt][2] + s10, c[nt][3] + s11);
    }
}

// ---------------------------------------------------------------------------
extern "C" void kernel_launch(void* const* d_in, const int* in_sizes, int n_in,
                              void* d_out, int out_size) {
    const float* x   = (const float*)d_in[0];
    const float* W_A = (const float*)d_in[1];
    const float* b_A = (const float*)d_in[2];
    const float* W_B = (const float*)d_in[3];
    const float* b_B = (const float*)d_in[4];
    const float* W_C = (const float*)d_in[5];
    const float* b_C = (const float*)d_in[6];
    float* out = (float*)d_out;

    const int smA = (128 * 68 + 64 * 68) * sizeof(float);
    const int smB = (128 * 68 + 64 * 132 + 128 * 4) * sizeof(float);
    const int smC = CK_SMEM * sizeof(float);
    const int smO = KO_SMEM * sizeof(float);
    cudaFuncSetAttribute(k_projA, cudaFuncAttributeMaxDynamicSharedMemorySize, smA);
    cudaFuncSetAttribute(k_projB, cudaFuncAttributeMaxDynamicSharedMemorySize, smB);
    cudaFuncSetAttribute(k_chunk, cudaFuncAttributeMaxDynamicSharedMemorySize, smC);
    cudaFuncSetAttribute(k_out,   cudaFuncAttributeMaxDynamicSharedMemorySize, smO);

    k_projA<<<dim3(ROWS / 128, 4), 256, smA>>>(x, W_A, b_A);
    k_projB<<<dim3(ROWS / 128, 8), 256, smB>>>(x, W_B, b_B);
    k_chunk<<<BATCH * NCHUNK, 256, smC>>>();
    k_scan<<<BATCH, 32>>>();
    k_out<<<BATCH * NCHUNK, 256, smO>>>(x, W_C, b_C, out);
}

// round 5
// speedup vs baseline: 2.5841x; 1.1909x over previous
#include <cuda_runtime.h>

#define BATCH   8
#define SEQ     4096
#define DIM     64
#define DS      16
#define CHUNK   64
#define NCHUNK  (SEQ / CHUNK)        // 64
#define ROWS    (BATCH * SEQ)        // 32768

// Scratch (device globals; no allocations allowed)
__device__ float g_A [ROWS * 256];           // per-timestep A_t [row][i*16+l]
__device__ float g_Bx[ROWS * DS];            // per-timestep Bx_t
__device__ float g_P [BATCH * NCHUNK * 256]; // per-chunk cumulative transition
__device__ float g_v [BATCH * NCHUNK * DS];  // per-chunk aggregate input
__device__ float g_h0[BATCH * NCHUNK * DS];  // state entering each chunk
__device__ float g_H [ROWS * DS];            // h_t for every timestep

// ---------------------------------------------------------------------------
// helpers: tf32 convert + m16n8k8 tf32 mma
// ---------------------------------------------------------------------------
__device__ __forceinline__ float f2tf(float f) {
    unsigned u;
    asm("cvt.rna.tf32.f32 %0, %1;" : "=r"(u) : "f"(f));
    return __uint_as_float(u);
}
__device__ __forceinline__ void mma8(float* c,
                                     unsigned a0, unsigned a1, unsigned a2, unsigned a3,
                                     unsigned b0, unsigned b1) {
    asm volatile(
        "mma.sync.aligned.m16n8k8.row.col.f32.tf32.tf32.f32 "
        "{%0,%1,%2,%3},{%4,%5,%6,%7},{%8,%9},{%0,%1,%2,%3};"
        : "+f"(c[0]), "+f"(c[1]), "+f"(c[2]), "+f"(c[3])
        : "r"(a0), "r"(a1), "r"(a2), "r"(a3), "r"(b0), "r"(b1));
}
__device__ __forceinline__ unsigned fu(float f) { return __float_as_uint(f); }

__device__ __forceinline__ void cp16(void* smem_dst, const void* gsrc) {
    unsigned s = (unsigned)__cvta_generic_to_shared(smem_dst);
    asm volatile("cp.async.ca.shared.global [%0], [%1], 16;" :: "r"(s), "l"(gsrc));
}

// ---------------------------------------------------------------------------
// Kernel 1a (tensor): A = X @ W_A + b_A   ([32768,64] @ [64,256])
// ---------------------------------------------------------------------------
__global__ __launch_bounds__(256) void k_projA(const float* __restrict__ x,
                                               const float* __restrict__ W,
                                               const float* __restrict__ bias) {
    extern __shared__ float sm[];
    float* Xs = sm;             // [128][68]
    float* Ws = sm + 128 * 68;  // [64][68]
    const int tid = threadIdx.x;
    const int m0 = blockIdx.x * 128;
    const int n0 = blockIdx.y * 64;

#pragma unroll
    for (int it = 0; it < 8; it++) {
        int i4 = it * 256 + tid;
        int row = i4 >> 4, c4 = (i4 & 15) * 4;
        float4 v = *(const float4*)&x[(long)(m0 + row) * 64 + c4];
        Xs[row * 68 + c4 + 0] = f2tf(v.x);
        Xs[row * 68 + c4 + 1] = f2tf(v.y);
        Xs[row * 68 + c4 + 2] = f2tf(v.z);
        Xs[row * 68 + c4 + 3] = f2tf(v.w);
    }
#pragma unroll
    for (int it = 0; it < 4; it++) {
        int i4 = it * 256 + tid;
        int row = i4 >> 4, c4 = (i4 & 15) * 4;
        float4 v = *(const float4*)&W[(long)row * 256 + n0 + c4];
        Ws[row * 68 + c4 + 0] = f2tf(v.x);
        Ws[row * 68 + c4 + 1] = f2tf(v.y);
        Ws[row * 68 + c4 + 2] = f2tf(v.z);
        Ws[row * 68 + c4 + 3] = f2tf(v.w);
    }
    __syncthreads();

    const int wid = tid >> 5, lane = tid & 31;
    const int g = lane >> 2, tig = lane & 3;
    const int wm = wid & 3, wn = wid >> 2;
    const int mbase = wm * 32, nbase = wn * 32;

    float c[2][4][4];
#pragma unroll
    for (int mt = 0; mt < 2; mt++)
#pragma unroll
        for (int nt = 0; nt < 4; nt++)
#pragma unroll
            for (int j = 0; j < 4; j++) c[mt][nt][j] = 0.f;

#pragma unroll
    for (int ks = 0; ks < 8; ks++) {
        const int k0 = ks * 8;
        unsigned a[2][4];
#pragma unroll
        for (int mt = 0; mt < 2; mt++) {
            int r = mbase + mt * 16 + g;
            a[mt][0] = fu(Xs[r * 68 + k0 + tig]);
            a[mt][1] = fu(Xs[(r + 8) * 68 + k0 + tig]);
            a[mt][2] = fu(Xs[r * 68 + k0 + tig + 4]);
            a[mt][3] = fu(Xs[(r + 8) * 68 + k0 + tig + 4]);
        }
        unsigned b[4][2];
#pragma unroll
        for (int nt = 0; nt < 4; nt++) {
            int n = nbase + nt * 8 + g;
            b[nt][0] = fu(Ws[(k0 + tig) * 68 + n]);
            b[nt][1] = fu(Ws[(k0 + tig + 4) * 68 + n]);
        }
#pragma unroll
        for (int mt = 0; mt < 2; mt++)
#pragma unroll
            for (int nt = 0; nt < 4; nt++)
                mma8(c[mt][nt], a[mt][0], a[mt][1], a[mt][2], a[mt][3],
                     b[nt][0], b[nt][1]);
    }

#pragma unroll
    for (int mt = 0; mt < 2; mt++)
#pragma unroll
        for (int nt = 0; nt < 4; nt++) {
            int row = m0 + mbase + mt * 16 + g;
            int col = n0 + nbase + nt * 8 + tig * 2;
            float b0 = bias[col], b1 = bias[col + 1];
            *(float2*)&g_A[(long)row * 256 + col] =
                make_float2(c[mt][nt][0] + b0, c[mt][nt][1] + b1);
            *(float2*)&g_A[(long)(row + 8) * 256 + col] =
                make_float2(c[mt][nt][2] + b0, c[mt][nt][3] + b1);
        }
}

// ---------------------------------------------------------------------------
// Kernel 1b (tensor): Bm = X @ W_B + b_B fused with Bx = Bm . x
// ---------------------------------------------------------------------------
__global__ __launch_bounds__(256) void k_projB(const float* __restrict__ x,
                                               const float* __restrict__ W,
                                               const float* __restrict__ bias) {
    extern __shared__ float sm[];
    float* Xs  = sm;                        // [128][68]
    float* Ws  = sm + 128 * 68;             // [64][132]
    float* red = Ws + 64 * 132;             // [128][4]
    const int tid = threadIdx.x;
    const int m0 = blockIdx.x * 128;
    const int n0 = blockIdx.y * 128;

#pragma unroll
    for (int it = 0; it < 8; it++) {
        int i4 = it * 256 + tid;
        int row = i4 >> 4, c4 = (i4 & 15) * 4;
        float4 v = *(const float4*)&x[(long)(m0 + row) * 64 + c4];
        Xs[row * 68 + c4 + 0] = f2tf(v.x);
        Xs[row * 68 + c4 + 1] = f2tf(v.y);
        Xs[row * 68 + c4 + 2] = f2tf(v.z);
        Xs[row * 68 + c4 + 3] = f2tf(v.w);
    }
#pragma unroll
    for (int it = 0; it < 8; it++) {
        int i4 = it * 256 + tid;
        int row = i4 >> 5, c4 = (i4 & 31) * 4;
        float4 v = *(const float4*)&W[(long)row * 1024 + n0 + c4];
        Ws[row * 132 + c4 + 0] = f2tf(v.x);
        Ws[row * 132 + c4 + 1] = f2tf(v.y);
        Ws[row * 132 + c4 + 2] = f2tf(v.z);
        Ws[row * 132 + c4 + 3] = f2tf(v.w);
    }
    __syncthreads();

    const int wid = tid >> 5, lane = tid & 31;
    const int g = lane >> 2, tig = lane & 3;
    const int wm = wid & 1, wn = wid >> 1;
    const int mbase = wm * 64, nbase = wn * 32;

    float c[4][4][4];
#pragma unroll
    for (int mt = 0; mt < 4; mt++)
#pragma unroll
        for (int nt = 0; nt < 4; nt++)
#pragma unroll
            for (int j = 0; j < 4; j++) c[mt][nt][j] = 0.f;

#pragma unroll
    for (int ks = 0; ks < 8; ks++) {
        const int k0 = ks * 8;
        unsigned a[4][4];
#pragma unroll
        for (int mt = 0; mt < 4; mt++) {
            int r = mbase + mt * 16 + g;
            a[mt][0] = fu(Xs[r * 68 + k0 + tig]);
            a[mt][1] = fu(Xs[(r + 8) * 68 + k0 + tig]);
            a[mt][2] = fu(Xs[r * 68 + k0 + tig + 4]);
            a[mt][3] = fu(Xs[(r + 8) * 68 + k0 + tig + 4]);
        }
        unsigned b[4][2];
#pragma unroll
        for (int nt = 0; nt < 4; nt++) {
            int n = nbase + nt * 8 + g;
            b[nt][0] = fu(Ws[(k0 + tig) * 132 + n]);
            b[nt][1] = fu(Ws[(k0 + tig + 4) * 132 + n]);
        }
#pragma unroll
        for (int mt = 0; mt < 4; mt++)
#pragma unroll
            for (int nt = 0; nt < 4; nt++)
                mma8(c[mt][nt], a[mt][0], a[mt][1], a[mt][2], a[mt][3],
                     b[nt][0], b[nt][1]);
    }

    float bv0[4], bv1[4];
    int dl[4];
#pragma unroll
    for (int nt = 0; nt < 4; nt++) {
        int d0 = nbase + nt * 8 + tig * 2;
        dl[nt] = d0 & 63;
        bv0[nt] = bias[n0 + d0];
        bv1[nt] = bias[n0 + d0 + 1];
    }
#pragma unroll
    for (int mt = 0; mt < 4; mt++) {
        int r0 = mbase + mt * 16 + g;
        int r1 = r0 + 8;
        float p0 = 0.f, p1 = 0.f;
#pragma unroll
        for (int nt = 0; nt < 4; nt++) {
            float x00 = Xs[r0 * 68 + dl[nt]];
            float x01 = Xs[r0 * 68 + dl[nt] + 1];
            float x10 = Xs[r1 * 68 + dl[nt]];
            float x11 = Xs[r1 * 68 + dl[nt] + 1];
            p0 += (c[mt][nt][0] + bv0[nt]) * x00 + (c[mt][nt][1] + bv1[nt]) * x01;
            p1 += (c[mt][nt][2] + bv0[nt]) * x10 + (c[mt][nt][3] + bv1[nt]) * x11;
        }
        p0 += __shfl_xor_sync(0xffffffffu, p0, 1, 4);
        p0 += __shfl_xor_sync(0xffffffffu, p0, 2, 4);
        p1 += __shfl_xor_sync(0xffffffffu, p1, 1, 4);
        p1 += __shfl_xor_sync(0xffffffffu, p1, 2, 4);
        if (tig == 0) {
            red[r0 * 4 + wn] = p0;
            red[r1 * 4 + wn] = p1;
        }
    }
    __syncthreads();
    {
        int r = tid >> 1, grp = tid & 1;
        float bx = red[r * 4 + grp * 2] + red[r * 4 + grp * 2 + 1];
        int n_idx = blockIdx.y * 2 + grp;
        g_Bx[(long)(m0 + r) * DS + n_idx] = bx;
    }
}

// ---------------------------------------------------------------------------
// Kernel 1c: per-chunk P,v via binary tree combine (6 levels)
// ---------------------------------------------------------------------------
#define MSTRIDE 272
#define CK_BUFA 0
#define CK_BUFB (32 * MSTRIDE)
#define CK_VX   (2 * 32 * MSTRIDE)
#define CK_VA   (CK_VX + 64 * 16)
#define CK_VB   (CK_VA + 32 * 16)
#define CK_SMEM (CK_VB + 32 * 16)

__global__ __launch_bounds__(256) void k_chunk() {
    extern __shared__ float sm[];
    float* bufA = sm + CK_BUFA;
    float* bufB = sm + CK_BUFB;
    float* VX   = sm + CK_VX;
    float* Va   = sm + CK_VA;
    float* Vb   = sm + CK_VB;
    const int tid = threadIdx.x;
    const int bc = blockIdx.x;
    const long rowbase = (long)bc * CHUNK;

#pragma unroll
    for (int it = 0; it < 8; it++) {
        int i4 = it * 256 + tid;
        int m = i4 >> 6, e4 = (i4 & 63) * 4;
        *(float4*)&bufA[m * MSTRIDE + e4] =
            *(const float4*)&g_A[(rowbase + 2 * m) * 256 + e4];
    }
    *(float4*)&VX[tid * 4] = *(const float4*)&g_Bx[rowbase * DS + tid * 4];
    __syncthreads();

#pragma unroll
    for (int rep = 0; rep < 2; rep++) {
        int r = rep * 256 + tid;
        int m = r >> 4, i = r & 15;
        const float* arow = &g_A[(rowbase + 2 * m + 1) * 256 + i * 16];
        float4 a0 = *(const float4*)&arow[0];
        float4 a1 = *(const float4*)&arow[4];
        float4 a2 = *(const float4*)&arow[8];
        float4 a3 = *(const float4*)&arow[12];
        float av[16] = {a0.x, a0.y, a0.z, a0.w, a1.x, a1.y, a1.z, a1.w,
                        a2.x, a2.y, a2.z, a2.w, a3.x, a3.y, a3.z, a3.w};
        float acc[16];
#pragma unroll
        for (int l = 0; l < 16; l++) acc[l] = 0.f;
        float accv = VX[(2 * m + 1) * 16 + i];
#pragma unroll
        for (int q = 0; q < 16; q++) {
            float aq = av[q];
            float4 b0 = *(const float4*)&bufA[m * MSTRIDE + q * 16 + 0];
            float4 b1 = *(const float4*)&bufA[m * MSTRIDE + q * 16 + 4];
            float4 b2 = *(const float4*)&bufA[m * MSTRIDE + q * 16 + 8];
            float4 b3 = *(const float4*)&bufA[m * MSTRIDE + q * 16 + 12];
            acc[0]  += aq * b0.x; acc[1]  += aq * b0.y;
            acc[2]  += aq * b0.z; acc[3]  += aq * b0.w;
            acc[4]  += aq * b1.x; acc[5]  += aq * b1.y;
            acc[6]  += aq * b1.z; acc[7]  += aq * b1.w;
            acc[8]  += aq * b2.x; acc[9]  += aq * b2.y;
            acc[10] += aq * b2.z; acc[11] += aq * b2.w;
            acc[12] += aq * b3.x; acc[13] += aq * b3.y;
            acc[14] += aq * b3.z; acc[15] += aq * b3.w;
            accv += aq * VX[2 * m * 16 + q];
        }
#pragma unroll
        for (int l4 = 0; l4 < 4; l4++)
            *(float4*)&bufB[m * MSTRIDE + i * 16 + l4 * 4] =
                make_float4(acc[l4 * 4], acc[l4 * 4 + 1],
                            acc[l4 * 4 + 2], acc[l4 * 4 + 3]);
        Vb[m * 16 + i] = accv;
    }
    __syncthreads();

    float* src = bufB; float* dst = bufA;
    float* vs = Vb;    float* vd = Va;
#pragma unroll
    for (int lev = 1; lev <= 5; lev++) {
        int nmerge = 32 >> lev;
        int rows = nmerge * 16;
        if (tid < rows) {
            int m = tid >> 4, i = tid & 15;
            const float* a1p = &src[(2 * m + 1) * MSTRIDE + i * 16];
            float4 a0 = *(const float4*)&a1p[0];
            float4 a1 = *(const float4*)&a1p[4];
            float4 a2 = *(const float4*)&a1p[8];
            float4 a3 = *(const float4*)&a1p[12];
            float av[16] = {a0.x, a0.y, a0.z, a0.w, a1.x, a1.y, a1.z, a1.w,
                            a2.x, a2.y, a2.z, a2.w, a3.x, a3.y, a3.z, a3.w};
            float acc[16];
#pragma unroll
            for (int l = 0; l < 16; l++) acc[l] = 0.f;
            float accv = vs[(2 * m + 1) * 16 + i];
#pragma unroll
            for (int q = 0; q < 16; q++) {
                float aq = av[q];
                const float* bp = &src[2 * m * MSTRIDE + q * 16];
                float4 b0 = *(const float4*)&bp[0];
                float4 b1 = *(const float4*)&bp[4];
                float4 b2 = *(const float4*)&bp[8];
                float4 b3 = *(const float4*)&bp[12];
                acc[0]  += aq * b0.x; acc[1]  += aq * b0.y;
                acc[2]  += aq * b0.z; acc[3]  += aq * b0.w;
                acc[4]  += aq * b1.x; acc[5]  += aq * b1.y;
                acc[6]  += aq * b1.z; acc[7]  += aq * b1.w;
                acc[8]  += aq * b2.x; acc[9]  += aq * b2.y;
                acc[10] += aq * b2.z; acc[11] += aq * b2.w;
                acc[12] += aq * b3.x; acc[13] += aq * b3.y;
                acc[14] += aq * b3.z; acc[15] += aq * b3.w;
                accv += aq * vs[2 * m * 16 + q];
            }
#pragma unroll
            for (int l4 = 0; l4 < 4; l4++)
                *(float4*)&dst[m * MSTRIDE + i * 16 + l4 * 4] =
                    make_float4(acc[l4 * 4], acc[l4 * 4 + 1],
                                acc[l4 * 4 + 2], acc[l4 * 4 + 3]);
            vd[m * 16 + i] = accv;
        }
        __syncthreads();
        float* t = src; src = dst; dst = t;
        float* tv = vs; vs = vd; vd = tv;
    }

    g_P[(long)bc * 256 + tid] = src[tid];
    if (tid < 16) g_v[bc * DS + tid] = vs[tid];
}

// ---------------------------------------------------------------------------
// Kernel 2: inter-chunk scan. One block per batch; cp.async ring, depth 4.
// ---------------------------------------------------------------------------
#define RING_ROW 20
#define RING_STAGE (16 * RING_ROW + 16)

__global__ __launch_bounds__(32) void k_scan() {
    __shared__ float ring[4][RING_STAGE];
    const int b = blockIdx.x;
    const int lane = threadIdx.x;
    const long base = (long)b * NCHUNK;

#pragma unroll
    for (int c = 0; c < 4; c++) {
        int slot = c & 3;
        if (lane < 16) {
            const float* src = &g_P[(base + c) * 256 + lane * 16];
#pragma unroll
            for (int j = 0; j < 4; j++)
                cp16(&ring[slot][lane * RING_ROW + j * 4], src + j * 4);
        }
        if (lane < 4)
            cp16(&ring[slot][16 * RING_ROW + lane * 4],
                 &g_v[(base + c) * DS + lane * 4]);
        asm volatile("cp.async.commit_group;");
    }

    float h[16];
#pragma unroll
    for (int q = 0; q < 16; q++) h[q] = 0.f;
    float mine = 0.f;

    for (int c = 0; c < NCHUNK; c++) {
        asm volatile("cp.async.wait_group 3;");
        __syncwarp();
        float hn = 0.f;
        if (lane < 16) {
            g_h0[(base + c) * DS + lane] = mine;
            const float* R = &ring[c & 3][lane * RING_ROW];
            float4 p0 = *(const float4*)&R[0];
            float4 p1 = *(const float4*)&R[4];
            float4 p2 = *(const float4*)&R[8];
            float4 p3 = *(const float4*)&R[12];
            float v = ring[c & 3][16 * RING_ROW + lane];
            float s0 = v + p0.x * h[0] + p0.y * h[1] + p0.z * h[2] + p0.w * h[3];
            float s1 = p1.x * h[4] + p1.y * h[5] + p1.z * h[6] + p1.w * h[7];
            float s2 = p2.x * h[8] + p2.y * h[9] + p2.z * h[10] + p2.w * h[11];
            float s3 = p3.x * h[12] + p3.y * h[13] + p3.z * h[14] + p3.w * h[15];
            hn = (s0 + s1) + (s2 + s3);
            mine = hn;
        }
#pragma unroll
        for (int q = 0; q < 16; q++)
            h[q] = __shfl_sync(0xffffffffu, hn, q);
        if (c + 4 < NCHUNK) {
            int slot = c & 3;
            if (lane < 16) {
                const float* src = &g_P[(base + c + 4) * 256 + lane * 16];
#pragma unroll
                for (int j = 0; j < 4; j++)
                    cp16(&ring[slot][lane * RING_ROW + j * 4], src + j * 4);
            }
            if (lane < 4)
                cp16(&ring[slot][16 * RING_ROW + lane * 4],
                     &g_v[(base + c + 4) * DS + lane * 4]);
        }
        asm volatile("cp.async.commit_group;");
    }
}

// ---------------------------------------------------------------------------
// Kernel 2b: per-chunk replay -> g_H[t][n] for all timesteps.
// One warp per chunk; register replay, prefetch A and Bx one step ahead.
// ---------------------------------------------------------------------------
__global__ __launch_bounds__(32) void k_replay() {
    const int bc = blockIdx.x;
    const int lane = threadIdx.x;
    const long rowbase = (long)bc * CHUNK;

    float h[16];
#pragma unroll
    for (int q = 0; q < 16; q++) h[q] = g_h0[bc * DS + q];

    float4 a0 = {0,0,0,0}, a1 = a0, a2 = a0, a3 = a0;
    float bx = 0.f;
    if (lane < 16) {
        const float* Arow = &g_A[rowbase * 256 + lane * 16];
        a0 = *(const float4*)&Arow[0];
        a1 = *(const float4*)&Arow[4];
        a2 = *(const float4*)&Arow[8];
        a3 = *(const float4*)&Arow[12];
        bx = g_Bx[rowbase * DS + lane];
    }
    for (int t = 0; t < CHUNK; t++) {
        float4 n0 = a0, n1 = a1, n2 = a2, n3 = a3;
        float bxn = bx;
        if (lane < 16 && t + 1 < CHUNK) {
            const float* An = &g_A[(rowbase + t + 1) * 256 + lane * 16];
            n0 = *(const float4*)&An[0];
            n1 = *(const float4*)&An[4];
            n2 = *(const float4*)&An[8];
            n3 = *(const float4*)&An[12];
            bxn = g_Bx[(rowbase + t + 1) * DS + lane];
        }
        float hn = 0.f;
        if (lane < 16) {
            float s0 = bx + a0.x * h[0] + a0.y * h[1] + a0.z * h[2] + a0.w * h[3];
            float s1 = a1.x * h[4] + a1.y * h[5] + a1.z * h[6] + a1.w * h[7];
            float s2 = a2.x * h[8] + a2.y * h[9] + a2.z * h[10] + a2.w * h[11];
            float s3 = a3.x * h[12] + a3.y * h[13] + a3.z * h[14] + a3.w * h[15];
            hn = (s0 + s1) + (s2 + s3);
            g_H[(rowbase + t) * DS + lane] = hn;
        }
#pragma unroll
        for (int q = 0; q < 16; q++)
            h[q] = __shfl_sync(0xffffffffu, hn, q);
        a0 = n0; a1 = n1; a2 = n2; a3 = n3; bx = bxn;
    }
}

// ---------------------------------------------------------------------------
// Kernel 3 (tensor): out[m,d] = sum_n h[m,n] * (x @ W_C[:,n,:])[m,d]
//                              + sum_n h[m,n] * b_C[n*64+d]
// BM=128, per-n GEMM (N=64, K=64) with in-register h-fold; W reg-pipelined.
// ---------------------------------------------------------------------------
#define KC_WS   (128 * 68)
#define KC_HS   (KC_WS + 64 * 68)
#define KC_SMEM (KC_HS + 128 * 17)

__global__ __launch_bounds__(256) void k_outC(const float* __restrict__ x,
                                              const float* __restrict__ W_C,
                                              const float* __restrict__ b_C,
                                              float* __restrict__ out) {
    extern __shared__ float sm[];
    float* Xs = sm;             // [128][68] tf32 x
    float* Ws = sm + KC_WS;     // [64][68]  tf32 W_C slice (reused for b_C)
    float* Hs = sm + KC_HS;     // [128][17] fp32 h
    const int tid = threadIdx.x;
    const int m0 = blockIdx.x * 128;

#pragma unroll
    for (int it = 0; it < 8; it++) {
        int i4 = it * 256 + tid;
        int row = i4 >> 4, c4 = (i4 & 15) * 4;
        float4 v = *(const float4*)&x[(long)(m0 + row) * 64 + c4];
        Xs[row * 68 + c4 + 0] = f2tf(v.x);
        Xs[row * 68 + c4 + 1] = f2tf(v.y);
        Xs[row * 68 + c4 + 2] = f2tf(v.z);
        Xs[row * 68 + c4 + 3] = f2tf(v.w);
    }
#pragma unroll
    for (int it = 0; it < 2; it++) {          // 128x16 h: 512 float4
        int i4 = it * 256 + tid;
        int row = i4 >> 2, c4 = (i4 & 3) * 4;
        float4 v = *(const float4*)&g_H[(long)(m0 + row) * DS + c4];
        Hs[row * 17 + c4 + 0] = v.x;
        Hs[row * 17 + c4 + 1] = v.y;
        Hs[row * 17 + c4 + 2] = v.z;
        Hs[row * 17 + c4 + 3] = v.w;
    }

    // W-slice load indices (64x64 per n -> 1024 float4, 4 per thread)
    int wk[4], wd[4];
#pragma unroll
    for (int it = 0; it < 4; it++) {
        int i4 = it * 256 + tid;
        wk[it] = i4 >> 4;
        wd[it] = (i4 & 15) * 4;
    }
    float4 wreg[4];
#pragma unroll
    for (int it = 0; it < 4; it++)
        wreg[it] = *(const float4*)&W_C[(long)wk[it] * 1024 + wd[it]];   // n=0

    const int wid = tid >> 5, lane = tid & 31;
    const int g = lane >> 2, tig = lane & 3;
    const int wm = wid & 3, wn = wid >> 2;
    const int mbase = wm * 32, nbase = wn * 32;

    float oacc[2][4][4];
#pragma unroll
    for (int mt = 0; mt < 2; mt++)
#pragma unroll
        for (int nt = 0; nt < 4; nt++)
#pragma unroll
            for (int j = 0; j < 4; j++) oacc[mt][nt][j] = 0.f;

    for (int n = 0; n < 16; n++) {
        __syncthreads();   // previous GEMM done reading Ws (and iter-0: loads done)
#pragma unroll
        for (int it = 0; it < 4; it++) {
            Ws[wk[it] * 68 + wd[it] + 0] = f2tf(wreg[it].x);
            Ws[wk[it] * 68 + wd[it] + 1] = f2tf(wreg[it].y);
            Ws[wk[it] * 68 + wd[it] + 2] = f2tf(wreg[it].z);
            Ws[wk[it] * 68 + wd[it] + 3] = f2tf(wreg[it].w);
        }
        __syncthreads();
        if (n + 1 < 16) {
#pragma unroll
            for (int it = 0; it < 4; it++)
                wreg[it] = *(const float4*)
                    &W_C[(long)wk[it] * 1024 + (n + 1) * 64 + wd[it]];
        }

        float c[2][4][4];
#pragma unroll
        for (int mt = 0; mt < 2; mt++)
#pragma unroll
            for (int nt = 0; nt < 4; nt++)
#pragma unroll
                for (int j = 0; j < 4; j++) c[mt][nt][j] = 0.f;

#pragma unroll
        for (int ks = 0; ks < 8; ks++) {
            const int k0 = ks * 8;
            unsigned a[2][4];
#pragma unroll
            for (int mt = 0; mt < 2; mt++) {
                int r = mbase + mt * 16 + g;
                a[mt][0] = fu(Xs[r * 68 + k0 + tig]);
                a[mt][1] = fu(Xs[(r + 8) * 68 + k0 + tig]);
                a[mt][2] = fu(Xs[r * 68 + k0 + tig + 4]);
                a[mt][3] = fu(Xs[(r + 8) * 68 + k0 + tig + 4]);
            }
            unsigned b[4][2];
#pragma unroll
            for (int nt = 0; nt < 4; nt++) {
                int nn = nbase + nt * 8 + g;
                b[nt][0] = fu(Ws[(k0 + tig) * 68 + nn]);
                b[nt][1] = fu(Ws[(k0 + tig + 4) * 68 + nn]);
            }
#pragma unroll
            for (int mt = 0; mt < 2; mt++)
#pragma unroll
                for (int nt = 0; nt < 4; nt++)
                    mma8(c[mt][nt], a[mt][0], a[mt][1], a[mt][2], a[mt][3],
                         b[nt][0], b[nt][1]);
        }

        // fold with h (fp32)
#pragma unroll
        for (int mt = 0; mt < 2; mt++) {
            int r0 = mbase + mt * 16 + g;
            float ha = Hs[r0 * 17 + n];
            float hb = Hs[(r0 + 8) * 17 + n];
#pragma unroll
            for (int nt = 0; nt < 4; nt++) {
                oacc[mt][nt][0] += ha * c[mt][nt][0];
                oacc[mt][nt][1] += ha * c[mt][nt][1];
                oacc[mt][nt][2] += hb * c[mt][nt][2];
                oacc[mt][nt][3] += hb * c[mt][nt][3];
            }
        }
    }

    // bias: stage b_C (fp32) into Ws rows 0..15
    __syncthreads();
    {
        int nn = tid >> 4, c4 = (tid & 15) * 4;
        float4 v = *(const float4*)&b_C[nn * 64 + c4];
        Ws[nn * 68 + c4 + 0] = v.x;
        Ws[nn * 68 + c4 + 1] = v.y;
        Ws[nn * 68 + c4 + 2] = v.z;
        Ws[nn * 68 + c4 + 3] = v.w;
    }
    __syncthreads();

#pragma unroll
    for (int mt = 0; mt < 2; mt++) {
        int r0 = mbase + mt * 16 + g;
        int r1 = r0 + 8;
#pragma unroll
        for (int nt = 0; nt < 4; nt++) {
            int col = nbase + nt * 8 + tig * 2;
            float s00 = 0.f, s01 = 0.f, s10 = 0.f, s11 = 0.f;
#pragma unroll
            for (int nn = 0; nn < 16; nn++) {
                float ha = Hs[r0 * 17 + nn], hb = Hs[r1 * 17 + nn];
                float w0 = Ws[nn * 68 + col], w1 = Ws[nn * 68 + col + 1];
                s00 += ha * w0; s01 += ha * w1;
                s10 += hb * w0; s11 += hb * w1;
            }
            *(float2*)&out[(long)(m0 + r0) * 64 + col] =
                make_float2(oacc[mt][nt][0] + s00, oacc[mt][nt][1] + s01);
            *(float2*)&out[(long)(m0 + r1) * 64 + col] =
                make_float2(oacc[mt][nt][2] + s10, oacc[mt][nt][3] + s11);
        }
    }
}

// ---------------------------------------------------------------------------
extern "C" void kernel_launch(void* const* d_in, const int* in_sizes, int n_in,
                              void* d_out, int out_size) {
    const float* x   = (const float*)d_in[0];
    const float* W_A = (const float*)d_in[1];
    const float* b_A = (const float*)d_in[2];
    const float* W_B = (const float*)d_in[3];
    const float* b_B = (const float*)d_in[4];
    const float* W_C = (const float*)d_in[5];
    const float* b_C = (const float*)d_in[6];
    float* out = (float*)d_out;

    const int smA = (128 * 68 + 64 * 68) * sizeof(float);
    const int smB = (128 * 68 + 64 * 132 + 128 * 4) * sizeof(float);
    const int smC = CK_SMEM * sizeof(float);
    const int smO = KC_SMEM * sizeof(float);
    cudaFuncSetAttribute(k_projA, cudaFuncAttributeMaxDynamicSharedMemorySize, smA);
    cudaFuncSetAttribute(k_projB, cudaFuncAttributeMaxDynamicSharedMemorySize, smB);
    cudaFuncSetAttribute(k_chunk, cudaFuncAttributeMaxDynamicSharedMemorySize, smC);
    cudaFuncSetAttribute(k_outC,  cudaFuncAttributeMaxDynamicSharedMemorySize, smO);

    k_projA<<<dim3(ROWS / 128, 4), 256, smA>>>(x, W_A, b_A);
    k_projB<<<dim3(ROWS / 128, 8), 256, smB>>>(x, W_B, b_B);
    k_chunk<<<BATCH * NCHUNK, 256, smC>>>();
    k_scan<<<BATCH, 32>>>();
    k_replay<<<BATCH * NCHUNK, 32>>>();
    k_outC<<<ROWS / 128, 256, smO>>>(x, W_C, b_C, out);
}